// round 2
// baseline (speedup 1.0000x reference)
#include <cuda_runtime.h>
#include <cuda_bf16.h>
#include <cstdint>

#define NNODE 4096
#define CDIM  768
#define HDIM  512
#define ODIM  50
#define OPAD  64

// ---------------- device scratch (static: no allocations allowed) -------------
__device__ float g_sim[(size_t)NNODE * NNODE];   // 64MB: sim -> adj -> norm_adj (in place)
__device__ float g_xw1[(size_t)NNODE * HDIM];
__device__ float g_h  [(size_t)NNODE * HDIM];
__device__ float g_hw2[(size_t)NNODE * OPAD];
__device__ float g_g  [(size_t)NNODE * OPAD];
__device__ float g_w2p[(size_t)HDIM * OPAD];
__device__ float g_b2p[OPAD];
__device__ float g_dinv[NNODE];
__device__ int   g_lab[NNODE];
__device__ double g_s;
__device__ unsigned long long g_cnt;
__device__ float g_thr;

// ---------------- labels: detect int32 vs int64 storage, normalize -----------
// If the buffer holds int64 values (0/1), every odd int32 word is the zero high
// half. If it holds int32 values, odd words are labels[1,3,...] (~half ones).
__global__ void lab_k(const int* __restrict__ p) {
    __shared__ int sh[256];
    int o = 0;
    for (int i = threadIdx.x; i < NNODE / 2; i += 256) o |= p[2 * i + 1];
    sh[threadIdx.x] = o;
    __syncthreads();
    for (int off = 128; off > 0; off >>= 1) {
        if (threadIdx.x < off) sh[threadIdx.x] |= sh[threadIdx.x + off];
        __syncthreads();
    }
    const bool is32 = (sh[0] != 0);
    for (int i = threadIdx.x; i < NNODE; i += 256)
        g_lab[i] = is32 ? p[i] : p[2 * i];   // little-endian low word of int64
}

// ---------------- prep: zero accumulators, pad W2/b2 to OPAD ------------------
__global__ void prep_kernel(const float* __restrict__ W2, const float* __restrict__ b2) {
    size_t idx = (size_t)blockIdx.x * blockDim.x + threadIdx.x;
    if (idx == 0) { g_s = 0.0; g_cnt = 0ULL; }
    if (idx < OPAD) g_b2p[idx] = (idx < ODIM) ? b2[idx] : 0.f;
    size_t tot = (size_t)HDIM * OPAD;
    for (size_t t = idx; t < tot; t += (size_t)gridDim.x * blockDim.x) {
        int k = (int)(t / OPAD), n = (int)(t % OPAD);
        g_w2p[t] = (n < ODIM) ? W2[(size_t)k * ODIM + n] : 0.f;
    }
}

// ---------------- SGEMM: C[M,Nn] = A[M,K] * B  (NT: B=[Nn,K], else B=[K,Nn]) --
#define BM 128
#define BN 128
#define BKK 8
#define TM 8
#define TN 8

template<bool NT, bool RELU, bool HASBIAS>
__global__ void __launch_bounds__(256, 2)
sgemm_k(const float* __restrict__ A, const float* __restrict__ B,
        const float* __restrict__ bias, float* __restrict__ C,
        int M, int Nn, int K, int ldb, int ldc)
{
    __shared__ float As[BKK][BM];
    __shared__ float Bs[BKK][BN + 4];

    const int bm = blockIdx.y * BM;
    const int bn = blockIdx.x * BN;
    const int tid = threadIdx.x;
    const int tx = tid & 15, ty = tid >> 4;

    float acc[TM][TN];
#pragma unroll
    for (int i = 0; i < TM; i++)
#pragma unroll
        for (int j = 0; j < TN; j++) acc[i][j] = 0.f;

    // A-tile load mapping: 128 rows x 8 k; each thread loads one float4
    const int arow = tid >> 1;
    const int acol = (tid & 1) * 4;
    const float* Ag = A + (size_t)(bm + arow) * K + acol;

    // B-tile mappings
    const int bkr = tid >> 5;          // NN: k-row 0..7
    const int bnc = (tid & 31) * 4;    // NN: n-col 0..124
    const int bnr = tid >> 1;          // NT: n-row 0..127
    const int bkc = (tid & 1) * 4;     // NT: k-col 0 or 4

    for (int k0 = 0; k0 < K; k0 += BKK) {
        float4 av = *reinterpret_cast<const float4*>(Ag + k0);
        As[acol + 0][arow] = av.x;
        As[acol + 1][arow] = av.y;
        As[acol + 2][arow] = av.z;
        As[acol + 3][arow] = av.w;

        if (NT) {
            int gcol = bn + bnr;
            float4 bv = make_float4(0.f, 0.f, 0.f, 0.f);
            if (gcol < Nn)
                bv = *reinterpret_cast<const float4*>(B + (size_t)gcol * ldb + k0 + bkc);
            Bs[bkc + 0][bnr] = bv.x;
            Bs[bkc + 1][bnr] = bv.y;
            Bs[bkc + 2][bnr] = bv.z;
            Bs[bkc + 3][bnr] = bv.w;
        } else {
            int gcol = bn + bnc;
            float4 bv = make_float4(0.f, 0.f, 0.f, 0.f);
            if (gcol < Nn)
                bv = *reinterpret_cast<const float4*>(B + (size_t)(k0 + bkr) * ldb + gcol);
            Bs[bkr][bnc + 0] = bv.x;
            Bs[bkr][bnc + 1] = bv.y;
            Bs[bkr][bnc + 2] = bv.z;
            Bs[bkr][bnc + 3] = bv.w;
        }
        __syncthreads();

#pragma unroll
        for (int kk = 0; kk < BKK; kk++) {
            float a[TM], b[TN];
#pragma unroll
            for (int i = 0; i < TM; i++) a[i] = As[kk][ty * TM + i];
#pragma unroll
            for (int j = 0; j < TN; j++) b[j] = Bs[kk][tx * TN + j];
#pragma unroll
            for (int i = 0; i < TM; i++)
#pragma unroll
                for (int j = 0; j < TN; j++) acc[i][j] += a[i] * b[j];
        }
        __syncthreads();
    }

#pragma unroll
    for (int i = 0; i < TM; i++) {
        int gm = bm + ty * TM + i;
        if (gm >= M) continue;
#pragma unroll
        for (int j = 0; j < TN; j++) {
            int gn = bn + tx * TN + j;
            if (gn < Nn) {
                float v = acc[i][j];
                if (HASBIAS) v += bias[gn];
                if (RELU) v = fmaxf(v, 0.f);
                C[(size_t)gm * ldc + gn] = v;
            }
        }
    }
}

// ---------------- threshold: sum sim over cross-label pairs -------------------
__global__ void thr_reduce_k() {
    __shared__ double sh_s[256];
    __shared__ unsigned long long sh_c[256];
    double s = 0.0;
    unsigned long long c = 0ULL;
    size_t tot = (size_t)NNODE * NNODE;
    for (size_t idx = (size_t)blockIdx.x * blockDim.x + threadIdx.x; idx < tot;
         idx += (size_t)gridDim.x * blockDim.x) {
        int i = (int)(idx >> 12), j = (int)(idx & (NNODE - 1));
        if (g_lab[i] != g_lab[j]) { s += (double)g_sim[idx]; c++; }
    }
    sh_s[threadIdx.x] = s;
    sh_c[threadIdx.x] = c;
    __syncthreads();
    for (int off = 128; off > 0; off >>= 1) {
        if (threadIdx.x < off) {
            sh_s[threadIdx.x] += sh_s[threadIdx.x + off];
            sh_c[threadIdx.x] += sh_c[threadIdx.x + off];
        }
        __syncthreads();
    }
    if (threadIdx.x == 0) {
        atomicAdd(&g_s, sh_s[0]);
        atomicAdd(&g_cnt, sh_c[0]);
    }
}

__global__ void thr_final_k() {
    g_thr = (g_cnt > 0ULL) ? (float)(g_s / (double)g_cnt) : 0.f;
}

// ---------------- mask + degree: sim -> adj (in place), loss_mask, dinv ------
__global__ void mask_deg_k(float* __restrict__ loss_out, int write_loss) {
    const int i = blockIdx.x;
    const int li = g_lab[i];
    const float thr = g_thr;
    int deg = 0;
    size_t row = (size_t)i * NNODE;
    for (int j = threadIdx.x; j < NNODE; j += blockDim.x) {
        float sv = g_sim[row + j];
        bool same = (g_lab[j] == li) && (j != i);
        bool edge = same && (sv <= thr);
        g_sim[row + j] = edge ? 1.f : 0.f;
        if (write_loss) loss_out[row + j] = (edge && (i < j)) ? 1.f : 0.f;
        deg += edge ? 1 : 0;
    }
    __shared__ int sh[256];
    sh[threadIdx.x] = deg;
    __syncthreads();
    for (int off = 128; off > 0; off >>= 1) {
        if (threadIdx.x < off) sh[threadIdx.x] += sh[threadIdx.x + off];
        __syncthreads();
    }
    if (threadIdx.x == 0) g_dinv[i] = rsqrtf((float)(sh[0] + 1));
}

// ---------------- normalize: adj -> D^-1/2 (A+I) D^-1/2 (in place) -----------
__global__ void normalize_k() {
    size_t tot = (size_t)NNODE * NNODE;
    for (size_t idx = (size_t)blockIdx.x * blockDim.x + threadIdx.x; idx < tot;
         idx += (size_t)gridDim.x * blockDim.x) {
        int i = (int)(idx >> 12), j = (int)(idx & (NNODE - 1));
        float a = g_sim[idx] + ((i == j) ? 1.f : 0.f);
        g_sim[idx] = (g_dinv[i] * a) * g_dinv[j];
    }
}

// ---------------- f_g writer + x copy ----------------------------------------
__global__ void fg_write_k(const float* __restrict__ x, float* __restrict__ fg,
                           float* __restrict__ xout) {
    const int FDIM = CDIM + ODIM;
    size_t tot = (size_t)NNODE * FDIM;
    for (size_t idx = (size_t)blockIdx.x * blockDim.x + threadIdx.x; idx < tot;
         idx += (size_t)gridDim.x * blockDim.x) {
        int i = (int)(idx / FDIM), c = (int)(idx % FDIM);
        fg[idx] = (c < CDIM) ? x[(size_t)i * CDIM + c]
                             : g_g[(size_t)i * OPAD + (c - CDIM)];
    }
    size_t totx = (size_t)NNODE * CDIM;
    for (size_t idx = (size_t)blockIdx.x * blockDim.x + threadIdx.x; idx < totx;
         idx += (size_t)gridDim.x * blockDim.x)
        xout[idx] = x[idx];
}

// ---------------- final GEMV: out = [x, g] @ fcW + fcb ------------------------
__global__ void out_gemv_k(const float* __restrict__ x, const float* __restrict__ fcW,
                           const float* __restrict__ fcb, float* __restrict__ out) {
    const int i = blockIdx.x;
    float s = 0.f;
    for (int c = threadIdx.x; c < CDIM; c += blockDim.x)
        s += x[(size_t)i * CDIM + c] * fcW[c];
    for (int o = threadIdx.x; o < ODIM; o += blockDim.x)
        s += g_g[(size_t)i * OPAD + o] * fcW[CDIM + o];
    __shared__ float sh[256];
    sh[threadIdx.x] = s;
    __syncthreads();
    for (int off = 128; off > 0; off >>= 1) {
        if (threadIdx.x < off) sh[threadIdx.x] += sh[threadIdx.x + off];
        __syncthreads();
    }
    if (threadIdx.x == 0) out[i] = sh[0] + fcb[0];
}

// ---------------- launch ------------------------------------------------------
extern "C" void kernel_launch(void* const* d_in, const int* in_sizes, int n_in,
                              void* d_out, int out_size) {
    const float* x   = (const float*)d_in[0];
    const int*   lab = (const int*)d_in[1];    // int32 OR int64 storage (detected on device)
    const float* W1  = (const float*)d_in[2];
    const float* b1  = (const float*)d_in[3];
    const float* W2  = (const float*)d_in[4];
    const float* b2  = (const float*)d_in[5];
    const float* fcW = (const float*)d_in[6];
    const float* fcb = (const float*)d_in[7];
    (void)in_sizes; (void)n_in;

    const size_t SZ_OUT = NNODE;
    const size_t SZ_FG  = (size_t)NNODE * (CDIM + ODIM);
    const size_t SZ_LM  = (size_t)NNODE * NNODE;
    const size_t SZ_X   = (size_t)NNODE * CDIM;
    const bool full = ((size_t)out_size >= SZ_OUT + SZ_FG + SZ_LM + SZ_X);

    float* o_out = (float*)d_out;
    float* o_fg  = o_out + SZ_OUT;
    float* o_lm  = o_fg + SZ_FG;
    float* o_x   = o_lm + SZ_LM;

    float* simp; cudaGetSymbolAddress((void**)&simp, g_sim);
    float* xw1p; cudaGetSymbolAddress((void**)&xw1p, g_xw1);
    float* hp;   cudaGetSymbolAddress((void**)&hp,   g_h);
    float* hw2p; cudaGetSymbolAddress((void**)&hw2p, g_hw2);
    float* gp;   cudaGetSymbolAddress((void**)&gp,   g_g);
    float* w2pp; cudaGetSymbolAddress((void**)&w2pp, g_w2p);
    float* b2pp; cudaGetSymbolAddress((void**)&b2pp, g_b2p);

    // 0. labels normalize + prep
    lab_k<<<1, 256>>>(lab);
    prep_kernel<<<128, 256>>>(W2, b2);

    // 1. sim = x @ x^T   (NT)  [4096 x 4096 x 768]
    {
        dim3 grid(NNODE / BN, NNODE / BM);
        sgemm_k<true, false, false><<<grid, 256>>>(x, x, nullptr, simp,
                                                   NNODE, NNODE, CDIM, CDIM, NNODE);
    }

    // 2. threshold
    thr_reduce_k<<<2048, 256>>>();
    thr_final_k<<<1, 1>>>();

    // 3. mask + degree (sim -> adj in place, loss_mask out, dinv)
    mask_deg_k<<<NNODE, 256>>>(full ? o_lm : nullptr, full ? 1 : 0);

    // 4. normalize adj -> norm_adj (in place)
    normalize_k<<<8192, 256>>>();

    // 5. xw1 = x @ W1    (NN)  [4096 x 512 x 768]
    {
        dim3 grid((HDIM + BN - 1) / BN, NNODE / BM);
        sgemm_k<false, false, false><<<grid, 256>>>(x, W1, nullptr, xw1p,
                                                    NNODE, HDIM, CDIM, HDIM, HDIM);
    }

    // 6. h = relu(norm_adj @ xw1 + b1)  [4096 x 512 x 4096]
    {
        dim3 grid((HDIM + BN - 1) / BN, NNODE / BM);
        sgemm_k<false, true, true><<<grid, 256>>>(simp, xw1p, b1, hp,
                                                  NNODE, HDIM, NNODE, HDIM, HDIM);
    }

    // 7. hw2 = h @ W2pad  [4096 x 64 x 512]
    {
        dim3 grid((OPAD + BN - 1) / BN, NNODE / BM);
        sgemm_k<false, false, false><<<grid, 256>>>(hp, w2pp, nullptr, hw2p,
                                                    NNODE, OPAD, HDIM, OPAD, OPAD);
    }

    // 8. g = norm_adj @ hw2 + b2pad  [4096 x 64 x 4096]
    {
        dim3 grid((OPAD + BN - 1) / BN, NNODE / BM);
        sgemm_k<false, false, true><<<grid, 256>>>(simp, hw2p, b2pp, gp,
                                                   NNODE, OPAD, NNODE, OPAD, OPAD);
    }

    // 9. f_g + x copy (only when full output requested)
    if (full) fg_write_k<<<4096, 256>>>(x, o_fg, o_x);

    // 10. out = f_g @ fcW + fcb
    out_gemv_k<<<NNODE, 256>>>(x, fcW, fcb, o_out);
}

// round 4
// speedup vs baseline: 4.2062x; 4.2062x over previous
#include <cuda_runtime.h>
#include <cuda_bf16.h>
#include <cstdint>

#define NNODE 4096
#define CDIM  768
#define HDIM  512
#define ODIM  50
#define OPAD  64

#define EPI_SIM  0
#define EPI_XW1T 1
#define EPI_H    2
#define EPI_HW2T 3
#define EPI_G    4

#define CAND_CAP 65536

// ---------------- device scratch (static: no allocations allowed) -------------
__device__ __align__(16) float         g_sim[(size_t)NNODE * NNODE];
__device__ __align__(16) __nv_bfloat16 g_a01[(size_t)NNODE * NNODE];
__device__ __align__(16) __nv_bfloat16 g_xh[(size_t)NNODE * CDIM],   g_xl[(size_t)NNODE * CDIM];
__device__ __align__(16) __nv_bfloat16 g_w1th[(size_t)HDIM * CDIM],  g_w1tl[(size_t)HDIM * CDIM];
__device__ __align__(16) __nv_bfloat16 g_w2th[(size_t)OPAD * HDIM],  g_w2tl[(size_t)OPAD * HDIM];
__device__ __align__(16) __nv_bfloat16 g_xw1th[(size_t)HDIM * NNODE], g_xw1tl[(size_t)HDIM * NNODE];
__device__ __align__(16) __nv_bfloat16 g_hh[(size_t)NNODE * HDIM],   g_hl[(size_t)NNODE * HDIM];
__device__ __align__(16) __nv_bfloat16 g_hw2th[(size_t)OPAD * NNODE], g_hw2tl[(size_t)OPAD * NNODE];
__device__ __align__(16) float g_g[(size_t)NNODE * OPAD];
__device__ float g_b2p[OPAD];
__device__ float g_dinv[NNODE];
__device__ int   g_lab[NNODE];
__device__ double g_s;
__device__ unsigned long long g_cnt;
__device__ float g_thr;
__device__ int   g_ncand;
__device__ int2  g_cand[CAND_CAP];

// ---------------- PTX helpers (all sm_80-compatible) ---------------------------
__device__ __forceinline__ uint32_t smem_u32(const void* p) {
    uint32_t a;
    asm("{ .reg .u64 t; cvta.to.shared.u64 t, %1; cvt.u32.u64 %0, t; }" : "=r"(a) : "l"(p));
    return a;
}
__device__ __forceinline__ void cp16(uint32_t d, const void* g) {
    asm volatile("cp.async.cg.shared.global [%0], [%1], 16;" :: "r"(d), "l"(g));
}
#define CP_COMMIT() asm volatile("cp.async.commit_group;" ::: "memory")
template<int N> __device__ __forceinline__ void cp_wait() {
    asm volatile("cp.async.wait_group %0;" :: "n"(N) : "memory");
}
__device__ __forceinline__ void ldm_x4(uint32_t* r, uint32_t addr) {
    asm volatile("ldmatrix.sync.aligned.m8n8.x4.shared.b16 {%0,%1,%2,%3}, [%4];"
        : "=r"(r[0]), "=r"(r[1]), "=r"(r[2]), "=r"(r[3]) : "r"(addr));
}
__device__ __forceinline__ void mma16816(float* c, const uint32_t* a, const uint32_t* b) {
    asm volatile(
        "mma.sync.aligned.m16n8k16.row.col.f32.bf16.bf16.f32 "
        "{%0,%1,%2,%3}, {%4,%5,%6,%7}, {%8,%9}, {%0,%1,%2,%3};"
        : "+f"(c[0]), "+f"(c[1]), "+f"(c[2]), "+f"(c[3])
        : "r"(a[0]), "r"(a[1]), "r"(a[2]), "r"(a[3]), "r"(b[0]), "r"(b[1]));
}

// ---------------- bf16 mma.sync GEMM: D[M,N] = sum_terms A[M,K] * B[N,K]^T ----
// A,B row-major K-major bf16. BM=128, BK=64, 2-stage cp.async pipeline,
// SW128-style XOR swizzle (conflict-free ldmatrix). 8 warps.
template<int TN, int NTERMS, int EPI>
__global__ void __launch_bounds__(256)
mma_gemm_k(const __nv_bfloat16* __restrict__ A0, const __nv_bfloat16* __restrict__ A1,
           const __nv_bfloat16* __restrict__ B0, const __nv_bfloat16* __restrict__ B1,
           int K, int lda, int ldb,
           float* __restrict__ fout,
           __nv_bfloat16* __restrict__ oh, __nv_bfloat16* __restrict__ ol,
           const float* __restrict__ bias)
{
    constexpr int WN = 32;
    constexpr int WM = (TN == 128) ? 64 : 32;
    constexpr int WX = TN / WN;            // warps along N
    constexpr int MI = WM / 16;
    constexpr int NJ = WN / 8;
    constexpr int ASTG = 128 * 128;        // 16KB per A stage
    constexpr int BSTG = TN * 128;
    constexpr int STG = ASTG + BSTG;

    extern __shared__ char smem[];
    __shared__ float s_red[256];
    const uint32_t sb = smem_u32(smem);
    const int tid = threadIdx.x;
    const int w = tid >> 5, lane = tid & 31;
    const int wm = (w / WX) * WM, wn = (w % WX) * WN;
    const int bm = blockIdx.y * 128;
    const int bn = blockIdx.x * TN;

    float acc[MI][NJ][4];
#pragma unroll
    for (int i = 0; i < MI; i++)
#pragma unroll
        for (int j = 0; j < NJ; j++)
#pragma unroll
            for (int q = 0; q < 4; q++) acc[i][j][q] = 0.f;

    const int kchunks = K >> 6;
    const int total = NTERMS * kchunks;

    // stage loader: term/kc select source; 16B chunks with XOR swizzle
    auto load_stage = [&](int s, int term, int kc) {
        const __nv_bfloat16* As = (term == 2) ? A1 : A0;
        const __nv_bfloat16* Bs = (term == 1) ? B1 : B0;
        const uint32_t sA = sb + s * STG;
        const uint32_t sB = sA + ASTG;
#pragma unroll
        for (int i = 0; i < 4; i++) {
            int q = i * 256 + tid;
            int r = q >> 3, c = q & 7;
            cp16(sA + r * 128 + (((c ^ (r & 7)) << 4)),
                 As + (size_t)(bm + r) * lda + kc * 64 + c * 8);
        }
#pragma unroll
        for (int i = 0; i < TN / 32; i++) {
            int q = i * 256 + tid;
            int r = q >> 3, c = q & 7;
            cp16(sB + r * 128 + (((c ^ (r & 7)) << 4)),
                 Bs + (size_t)(bn + r) * ldb + kc * 64 + c * 8);
        }
        CP_COMMIT();
    };

    load_stage(0, 0, 0);
    for (int ch = 0; ch < total; ch++) {
        if (ch + 1 < total) {
            int nt = (ch + 1) / kchunks, nkc = (ch + 1) % kchunks;
            load_stage((ch + 1) & 1, nt, nkc);
            cp_wait<1>();
        } else {
            cp_wait<0>();
        }
        __syncthreads();

        const uint32_t sA = sb + (ch & 1) * STG;
        const uint32_t sB = sA + ASTG;
#pragma unroll
        for (int kk = 0; kk < 4; kk++) {
            uint32_t a[MI][4];
#pragma unroll
            for (int i = 0; i < MI; i++) {
                int r = wm + i * 16 + (lane & 15);
                int c = kk * 2 + (lane >> 4);
                ldm_x4(a[i], sA + r * 128 + (((c ^ (r & 7)) << 4)));
            }
            uint32_t b[NJ][2];
#pragma unroll
            for (int jj = 0; jj < NJ / 2; jj++) {
                int mat = lane >> 3;
                int tile = 2 * jj + (mat >> 1);
                int kh = mat & 1;
                int n = wn + tile * 8 + (lane & 7);
                int c = kk * 2 + kh;
                uint32_t r4[4];
                ldm_x4(r4, sB + n * 128 + (((c ^ (n & 7)) << 4)));
                b[2 * jj][0] = r4[0]; b[2 * jj][1] = r4[1];
                b[2 * jj + 1][0] = r4[2]; b[2 * jj + 1][1] = r4[3];
            }
#pragma unroll
            for (int i = 0; i < MI; i++)
#pragma unroll
                for (int j = 0; j < NJ; j++)
                    mma16816(acc[i][j], a[i], b[j]);
        }
        __syncthreads();
    }

    // -------- epilogue -------------------------------------------------------
    const int g4 = lane >> 2, t4 = lane & 3;
    float part = 0.f;
#pragma unroll
    for (int i = 0; i < MI; i++) {
#pragma unroll
        for (int p = 0; p < 2; p++) {
            const int m = bm + wm + i * 16 + g4 + p * 8;
            float dl = 1.f;
            int li = 0;
            if (EPI == EPI_SIM) li = g_lab[m];
            else dl = g_dinv[m];
#pragma unroll
            for (int j = 0; j < NJ; j++) {
                const int n = bn + wn + j * 8 + t4 * 2;
                const float v0 = acc[i][j][2 * p + 0];
                const float v1 = acc[i][j][2 * p + 1];
                if (EPI == EPI_SIM) {
                    *reinterpret_cast<float2*>(g_sim + (size_t)m * NNODE + n) =
                        make_float2(v0, v1);
                    if (g_lab[n] != li)     part += v0;
                    if (g_lab[n + 1] != li) part += v1;
                } else if (EPI == EPI_XW1T || EPI == EPI_HW2T) {
                    float s0 = dl * v0, s1 = dl * v1;
                    __nv_bfloat16 h0 = __float2bfloat16(s0);
                    __nv_bfloat16 h1 = __float2bfloat16(s1);
                    oh[(size_t)n * NNODE + m] = h0;
                    ol[(size_t)n * NNODE + m] = __float2bfloat16(s0 - __bfloat162float(h0));
                    oh[(size_t)(n + 1) * NNODE + m] = h1;
                    ol[(size_t)(n + 1) * NNODE + m] = __float2bfloat16(s1 - __bfloat162float(h1));
                } else if (EPI == EPI_H) {
                    float s0 = fmaxf(dl * v0 + bias[n], 0.f);
                    float s1 = fmaxf(dl * v1 + bias[n + 1], 0.f);
                    __nv_bfloat16 h0 = __float2bfloat16(s0);
                    __nv_bfloat16 h1 = __float2bfloat16(s1);
                    *reinterpret_cast<__nv_bfloat162*>(oh + (size_t)m * HDIM + n) =
                        __nv_bfloat162(h0, h1);
                    *reinterpret_cast<__nv_bfloat162*>(ol + (size_t)m * HDIM + n) =
                        __nv_bfloat162(__float2bfloat16(s0 - __bfloat162float(h0)),
                                       __float2bfloat16(s1 - __bfloat162float(h1)));
                } else { // EPI_G
                    *reinterpret_cast<float2*>(fout + (size_t)m * OPAD + n) =
                        make_float2(dl * v0 + bias[n], dl * v1 + bias[n + 1]);
                }
            }
        }
    }
    if (EPI == EPI_SIM) {
        s_red[tid] = part;
        __syncthreads();
        for (int off = 128; off > 0; off >>= 1) {
            if (tid < off) s_red[tid] += s_red[tid + off];
            __syncthreads();
        }
        if (tid == 0) atomicAdd(&g_s, (double)s_red[0]);
    }
}

// ---------------- labels: detect int32 vs int64, normalize, exact pair count --
__global__ void lab_k(const int* __restrict__ p) {
    __shared__ int sh[256];
    __shared__ int so[256];
    int o = 0;
    for (int i = threadIdx.x; i < NNODE / 2; i += 256) o |= p[2 * i + 1];
    so[threadIdx.x] = o;
    __syncthreads();
    for (int off = 128; off > 0; off >>= 1) {
        if (threadIdx.x < off) so[threadIdx.x] |= so[threadIdx.x + off];
        __syncthreads();
    }
    const bool is32 = (so[0] != 0);
    int n1 = 0;
    for (int i = threadIdx.x; i < NNODE; i += 256) {
        int v = is32 ? p[i] : p[2 * i];
        g_lab[i] = v;
        n1 += (v != 0) ? 1 : 0;
    }
    sh[threadIdx.x] = n1;
    __syncthreads();
    for (int off = 128; off > 0; off >>= 1) {
        if (threadIdx.x < off) sh[threadIdx.x] += sh[threadIdx.x + off];
        __syncthreads();
    }
    if (threadIdx.x == 0) {
        unsigned long long c1 = (unsigned long long)sh[0];
        g_cnt = 2ULL * c1 * (unsigned long long)(NNODE - c1);
        g_s = 0.0;
        g_ncand = 0;
    }
}

// ---------------- split x into bf16 hi/lo -------------------------------------
__global__ void split_x_k(const float* __restrict__ x) {
    size_t tot = (size_t)NNODE * CDIM;
    for (size_t i = (size_t)blockIdx.x * blockDim.x + threadIdx.x; i < tot;
         i += (size_t)gridDim.x * blockDim.x) {
        float v = x[i];
        __nv_bfloat16 h = __float2bfloat16(v);
        g_xh[i] = h;
        g_xl[i] = __float2bfloat16(v - __bfloat162float(h));
    }
}

// ---------------- weights: transpose + split + pad ----------------------------
__global__ void prep_w_k(const float* __restrict__ W1, const float* __restrict__ W2,
                         const float* __restrict__ b2) {
    size_t idx = (size_t)blockIdx.x * blockDim.x + threadIdx.x;
    size_t stride = (size_t)gridDim.x * blockDim.x;
    if (idx < OPAD) g_b2p[idx] = (idx < ODIM) ? b2[idx] : 0.f;
    size_t t1 = (size_t)HDIM * CDIM;
    for (size_t t = idx; t < t1; t += stride) {
        int n = (int)(t / CDIM), k = (int)(t % CDIM);
        float v = W1[(size_t)k * HDIM + n];
        __nv_bfloat16 h = __float2bfloat16(v);
        g_w1th[t] = h;
        g_w1tl[t] = __float2bfloat16(v - __bfloat162float(h));
    }
    size_t t2 = (size_t)OPAD * HDIM;
    for (size_t t = idx; t < t2; t += stride) {
        int n = (int)(t / HDIM), k = (int)(t % HDIM);
        float v = (n < ODIM) ? W2[(size_t)k * ODIM + n] : 0.f;
        __nv_bfloat16 h = __float2bfloat16(v);
        g_w2th[t] = h;
        g_w2tl[t] = __float2bfloat16(v - __bfloat162float(h));
    }
}

__global__ void thr_final_k() {
    g_thr = (g_cnt > 0ULL) ? (float)(g_s / (double)g_cnt) : 0.f;
}

// ---------------- fixup: collect borderline same-label entries ----------------
__global__ void collect_k() {
    const float thr = g_thr;
    size_t tot = (size_t)NNODE * NNODE;
    for (size_t idx = (size_t)blockIdx.x * blockDim.x + threadIdx.x; idx < tot;
         idx += (size_t)gridDim.x * blockDim.x) {
        int i = (int)(idx >> 12), j = (int)(idx & (NNODE - 1));
        if (i != j && g_lab[i] == g_lab[j]) {
            float s = g_sim[idx];
            if (fabsf(s - thr) < 2e-3f) {
                int pos = atomicAdd(&g_ncand, 1);
                if (pos < CAND_CAP) g_cand[pos] = make_int2(i, j);
            }
        }
    }
}

// ---------------- fixup: exact fp32 dot for borderline entries ----------------
__global__ void fix_k(const float* __restrict__ x) {
    __shared__ float sh[256];
    int nc = g_ncand;
    if (nc > CAND_CAP) nc = CAND_CAP;
    for (int cid = blockIdx.x; cid < nc; cid += gridDim.x) {
        int2 c = g_cand[cid];
        const float* xi = x + (size_t)c.x * CDIM;
        const float* xj = x + (size_t)c.y * CDIM;
        float s = 0.f;
        for (int k = threadIdx.x; k < CDIM; k += 256) s += xi[k] * xj[k];
        sh[threadIdx.x] = s;
        __syncthreads();
        for (int off = 128; off > 0; off >>= 1) {
            if (threadIdx.x < off) sh[threadIdx.x] += sh[threadIdx.x + off];
            __syncthreads();
        }
        if (threadIdx.x == 0) g_sim[(size_t)c.x * NNODE + c.y] = sh[0];
        __syncthreads();
    }
}

// ---------------- mask: sim -> a01 bf16 (A+I), loss_mask, dinv ----------------
__global__ void mask_deg_k(float* __restrict__ loss_out, int write_loss) {
    const int i = blockIdx.x;
    const int li = g_lab[i];
    const float thr = g_thr;
    int deg = 0;
    const size_t row = (size_t)i * NNODE;
    for (int j0 = threadIdx.x * 4; j0 < NNODE; j0 += blockDim.x * 4) {
        float4 sv = *reinterpret_cast<const float4*>(g_sim + row + j0);
        float a[4], lm[4];
#pragma unroll
        for (int q = 0; q < 4; q++) {
            int j = j0 + q;
            float s = (q == 0) ? sv.x : (q == 1) ? sv.y : (q == 2) ? sv.z : sv.w;
            bool same = (g_lab[j] == li) && (j != i);
            bool edge = same && (s <= thr);
            deg += edge ? 1 : 0;
            a[q] = (edge || (j == i)) ? 1.f : 0.f;
            lm[q] = (edge && (i < j)) ? 1.f : 0.f;
        }
        __nv_bfloat162* ap = reinterpret_cast<__nv_bfloat162*>(g_a01 + row + j0);
        ap[0] = __floats2bfloat162_rn(a[0], a[1]);
        ap[1] = __floats2bfloat162_rn(a[2], a[3]);
        if (write_loss)
            *reinterpret_cast<float4*>(loss_out + row + j0) = make_float4(lm[0], lm[1], lm[2], lm[3]);
    }
    __shared__ int sh[256];
    sh[threadIdx.x] = deg;
    __syncthreads();
    for (int off = 128; off > 0; off >>= 1) {
        if (threadIdx.x < off) sh[threadIdx.x] += sh[threadIdx.x + off];
        __syncthreads();
    }
    if (threadIdx.x == 0) g_dinv[i] = rsqrtf((float)(sh[0] + 1));
}

// ---------------- f_g writer + x copy -----------------------------------------
__global__ void fg_write_k(const float* __restrict__ x, float* __restrict__ fg,
                           float* __restrict__ xout) {
    const int FDIM = CDIM + ODIM;
    size_t tot = (size_t)NNODE * FDIM;
    for (size_t idx = (size_t)blockIdx.x * blockDim.x + threadIdx.x; idx < tot;
         idx += (size_t)gridDim.x * blockDim.x) {
        int i = (int)(idx / FDIM), c = (int)(idx % FDIM);
        fg[idx] = (c < CDIM) ? x[(size_t)i * CDIM + c]
                             : g_g[(size_t)i * OPAD + (c - CDIM)];
    }
    size_t totx = (size_t)NNODE * CDIM;
    for (size_t idx = (size_t)blockIdx.x * blockDim.x + threadIdx.x; idx < totx;
         idx += (size_t)gridDim.x * blockDim.x)
        xout[idx] = x[idx];
}

// ---------------- final GEMV: out = [x, g] @ fcW + fcb ------------------------
__global__ void out_gemv_k(const float* __restrict__ x, const float* __restrict__ fcW,
                           const float* __restrict__ fcb, float* __restrict__ out) {
    const int i = blockIdx.x;
    float s = 0.f;
    for (int c = threadIdx.x; c < CDIM; c += blockDim.x)
        s += x[(size_t)i * CDIM + c] * fcW[c];
    for (int o = threadIdx.x; o < ODIM; o += blockDim.x)
        s += g_g[(size_t)i * OPAD + o] * fcW[CDIM + o];
    __shared__ float sh[256];
    sh[threadIdx.x] = s;
    __syncthreads();
    for (int off = 128; off > 0; off >>= 1) {
        if (threadIdx.x < off) sh[threadIdx.x] += sh[threadIdx.x + off];
        __syncthreads();
    }
    if (threadIdx.x == 0) out[i] = sh[0] + fcb[0];
}

// ---------------- launch ------------------------------------------------------
extern "C" void kernel_launch(void* const* d_in, const int* in_sizes, int n_in,
                              void* d_out, int out_size) {
    const float* x   = (const float*)d_in[0];
    const int*   lab = (const int*)d_in[1];
    const float* W1  = (const float*)d_in[2];
    const float* b1  = (const float*)d_in[3];
    const float* W2  = (const float*)d_in[4];
    const float* b2  = (const float*)d_in[5];
    const float* fcW = (const float*)d_in[6];
    const float* fcb = (const float*)d_in[7];
    (void)in_sizes; (void)n_in;

    const size_t SZ_OUT = NNODE;
    const size_t SZ_FG  = (size_t)NNODE * (CDIM + ODIM);
    const size_t SZ_LM  = (size_t)NNODE * NNODE;
    const size_t SZ_X   = (size_t)NNODE * CDIM;
    const bool full = ((size_t)out_size >= SZ_OUT + SZ_FG + SZ_LM + SZ_X);

    float* o_out = (float*)d_out;
    float* o_fg  = o_out + SZ_OUT;
    float* o_lm  = o_fg + SZ_FG;
    float* o_x   = o_lm + SZ_LM;

    __nv_bfloat16 *xh, *xl, *w1th, *w1tl, *w2th, *w2tl, *xw1th, *xw1tl, *hh, *hl, *hw2th, *hw2tl, *a01;
    float *gp, *b2pp;
    cudaGetSymbolAddress((void**)&xh, g_xh);       cudaGetSymbolAddress((void**)&xl, g_xl);
    cudaGetSymbolAddress((void**)&w1th, g_w1th);   cudaGetSymbolAddress((void**)&w1tl, g_w1tl);
    cudaGetSymbolAddress((void**)&w2th, g_w2th);   cudaGetSymbolAddress((void**)&w2tl, g_w2tl);
    cudaGetSymbolAddress((void**)&xw1th, g_xw1th); cudaGetSymbolAddress((void**)&xw1tl, g_xw1tl);
    cudaGetSymbolAddress((void**)&hh, g_hh);       cudaGetSymbolAddress((void**)&hl, g_hl);
    cudaGetSymbolAddress((void**)&hw2th, g_hw2th); cudaGetSymbolAddress((void**)&hw2tl, g_hw2tl);
    cudaGetSymbolAddress((void**)&a01, g_a01);
    cudaGetSymbolAddress((void**)&gp, g_g);
    cudaGetSymbolAddress((void**)&b2pp, g_b2p);

    const int SM128 = 2 * (128 * 128 + 128 * 128);  // 65536
    const int SM64  = 2 * (128 * 128 + 64 * 128);   // 49152
    cudaFuncSetAttribute(mma_gemm_k<128, 3, EPI_SIM>,  cudaFuncAttributeMaxDynamicSharedMemorySize, SM128);
    cudaFuncSetAttribute(mma_gemm_k<128, 3, EPI_XW1T>, cudaFuncAttributeMaxDynamicSharedMemorySize, SM128);
    cudaFuncSetAttribute(mma_gemm_k<128, 2, EPI_H>,    cudaFuncAttributeMaxDynamicSharedMemorySize, SM128);
    cudaFuncSetAttribute(mma_gemm_k<64, 3, EPI_HW2T>,  cudaFuncAttributeMaxDynamicSharedMemorySize, SM64);
    cudaFuncSetAttribute(mma_gemm_k<64, 2, EPI_G>,     cudaFuncAttributeMaxDynamicSharedMemorySize, SM64);

    // 0. labels + splits + weight prep
    lab_k<<<1, 256>>>(lab);
    split_x_k<<<512, 256>>>(x);
    prep_w_k<<<256, 256>>>(W1, W2, b2);

    // 1. sim = x @ x^T  (3-term bf16 split) + fused cross-label sum
    mma_gemm_k<128, 3, EPI_SIM><<<dim3(32, 32), 256, SM128>>>(
        xh, xl, xh, xl, CDIM, CDIM, CDIM, nullptr, nullptr, nullptr, nullptr);

    // 2. threshold, then exact-fp32 fixup of borderline entries
    thr_final_k<<<1, 1>>>();
    collect_k<<<4096, 256>>>();
    fix_k<<<512, 256>>>(x);

    // 3. mask: sim -> a01 (A+I, exact bf16), loss_mask, dinv
    mask_deg_k<<<NNODE, 256>>>(full ? o_lm : nullptr, full ? 1 : 0);

    // 4. xw1 = x @ W1; write (dinv_j * xw1)^T hi/lo   [512 x 4096]
    mma_gemm_k<128, 3, EPI_XW1T><<<dim3(HDIM / 128, 32), 256, SM128>>>(
        xh, xl, w1th, w1tl, CDIM, CDIM, CDIM, nullptr, xw1th, xw1tl, nullptr);

    // 5. h = relu(dinv_i * (a01 @ xw1t) + b1); write h hi/lo  [4096 x 512]
    mma_gemm_k<128, 2, EPI_H><<<dim3(HDIM / 128, 32), 256, SM128>>>(
        a01, a01, xw1th, xw1tl, NNODE, NNODE, NNODE, nullptr, hh, hl, b1);

    // 6. hw2 = h @ W2p; write (dinv_j * hw2)^T hi/lo  [64 x 4096]
    mma_gemm_k<64, 3, EPI_HW2T><<<dim3(1, 32), 256, SM64>>>(
        hh, hl, w2th, w2tl, HDIM, HDIM, HDIM, nullptr, hw2th, hw2tl, nullptr);

    // 7. g = dinv_i * (a01 @ hw2t) + b2p   [4096 x 64] fp32
    mma_gemm_k<64, 2, EPI_G><<<dim3(1, 32), 256, SM64>>>(
        a01, a01, hw2th, hw2tl, NNODE, NNODE, NNODE, gp, nullptr, nullptr, b2pp);

    // 8. outputs
    if (full) fg_write_k<<<4096, 256>>>(x, o_fg, o_x);
    out_gemv_k<<<NNODE, 256>>>(x, fcW, fcb, o_out);
}

// round 5
// speedup vs baseline: 4.9611x; 1.1795x over previous
#include <cuda_runtime.h>
#include <cuda_bf16.h>
#include <cstdint>

#define NNODE 4096
#define CDIM  768
#define HDIM  512
#define ODIM  50
#define OPAD  64

#define EPI_SIM  0
#define EPI_XW1T 1
#define EPI_H    2
#define EPI_HW2T 3
#define EPI_G    4

#define CAND_CAP 65536

// ---------------- device scratch (static: no allocations allowed) -------------
__device__ __align__(16) float         g_sim[(size_t)NNODE * NNODE];
__device__ __align__(16) __nv_bfloat16 g_a01[(size_t)NNODE * NNODE];
__device__ __align__(16) __nv_bfloat16 g_xh[(size_t)NNODE * CDIM],   g_xl[(size_t)NNODE * CDIM];
__device__ __align__(16) __nv_bfloat16 g_w1th[(size_t)HDIM * CDIM],  g_w1tl[(size_t)HDIM * CDIM];
__device__ __align__(16) __nv_bfloat16 g_w2th[(size_t)OPAD * HDIM],  g_w2tl[(size_t)OPAD * HDIM];
__device__ __align__(16) __nv_bfloat16 g_xw1th[(size_t)HDIM * NNODE], g_xw1tl[(size_t)HDIM * NNODE];
__device__ __align__(16) __nv_bfloat16 g_hh[(size_t)NNODE * HDIM],   g_hl[(size_t)NNODE * HDIM];
__device__ __align__(16) __nv_bfloat16 g_hw2th[(size_t)OPAD * NNODE], g_hw2tl[(size_t)OPAD * NNODE];
__device__ __align__(16) float g_g[(size_t)NNODE * OPAD];
__device__ float g_b2p[OPAD];
__device__ float g_dinv[NNODE];
__device__ int   g_lab[NNODE];
__device__ double g_s;
__device__ unsigned long long g_cnt;
__device__ float g_thr;
__device__ int   g_ncand;
__device__ int2  g_cand[CAND_CAP];

// ---------------- PTX helpers (all sm_80-compatible) ---------------------------
__device__ __forceinline__ uint32_t smem_u32(const void* p) {
    uint32_t a;
    asm("{ .reg .u64 t; cvta.to.shared.u64 t, %1; cvt.u32.u64 %0, t; }" : "=r"(a) : "l"(p));
    return a;
}
__device__ __forceinline__ void cp16(uint32_t d, const void* g) {
    asm volatile("cp.async.cg.shared.global [%0], [%1], 16;" :: "r"(d), "l"(g));
}
#define CP_COMMIT() asm volatile("cp.async.commit_group;" ::: "memory")
template<int N> __device__ __forceinline__ void cp_wait() {
    asm volatile("cp.async.wait_group %0;" :: "n"(N) : "memory");
}
__device__ __forceinline__ void ldm_x4(uint32_t* r, uint32_t addr) {
    asm volatile("ldmatrix.sync.aligned.m8n8.x4.shared.b16 {%0,%1,%2,%3}, [%4];"
        : "=r"(r[0]), "=r"(r[1]), "=r"(r[2]), "=r"(r[3]) : "r"(addr));
}
__device__ __forceinline__ void mma16816(float* c, const uint32_t* a, const uint32_t* b) {
    asm volatile(
        "mma.sync.aligned.m16n8k16.row.col.f32.bf16.bf16.f32 "
        "{%0,%1,%2,%3}, {%4,%5,%6,%7}, {%8,%9}, {%0,%1,%2,%3};"
        : "+f"(c[0]), "+f"(c[1]), "+f"(c[2]), "+f"(c[3])
        : "r"(a[0]), "r"(a[1]), "r"(a[2]), "r"(a[3]), "r"(b[0]), "r"(b[1]));
}

// ---------------- bf16 mma.sync GEMM: D[M,N] = sum_terms A[M,K] * B[N,K]^T ----
// A,B row-major K-major bf16. BM=128, BK=64, 2-stage cp.async pipeline,
// XOR swizzle (conflict-free ldmatrix). 8 warps.
// EPI_SIM: symmetric mode — grid enumerates upper-triangle blocks (bi<=bj);
// off-diagonal blocks are mirrored to the lower triangle via smem transpose.
template<int TN, int NTERMS, int EPI>
__global__ void __launch_bounds__(256)
mma_gemm_k(const __nv_bfloat16* __restrict__ A0, const __nv_bfloat16* __restrict__ A1,
           const __nv_bfloat16* __restrict__ B0, const __nv_bfloat16* __restrict__ B1,
           int K, int lda, int ldb,
           float* __restrict__ fout,
           __nv_bfloat16* __restrict__ oh, __nv_bfloat16* __restrict__ ol,
           const float* __restrict__ bias)
{
    constexpr int WN = 32;
    constexpr int WM = (TN == 128) ? 64 : 32;
    constexpr int WX = TN / WN;            // warps along N
    constexpr int MI = WM / 16;
    constexpr int NJ = WN / 8;
    constexpr int ASTG = 128 * 128;        // 16KB per A stage
    constexpr int BSTG = TN * 128;
    constexpr int STG = ASTG + BSTG;

    extern __shared__ char smem[];
    __shared__ float s_red[256];
    const uint32_t sb = smem_u32(smem);
    const int tid = threadIdx.x;
    const int w = tid >> 5, lane = tid & 31;
    const int wm = (w / WX) * WM, wn = (w % WX) * WN;

    int bm, bn;
    bool diag = true;
    if (EPI == EPI_SIM) {
        // unrank blockIdx.x -> (bi, bj), bi <= bj, 32x32 block grid
        int idx = blockIdx.x;
        int bi = 0;
        while (idx >= 32 - bi) { idx -= 32 - bi; bi++; }
        int bj = bi + idx;
        bm = bi * 128;
        bn = bj * 128;
        diag = (bi == bj);
    } else {
        bm = blockIdx.y * 128;
        bn = blockIdx.x * TN;
    }

    float acc[MI][NJ][4];
#pragma unroll
    for (int i = 0; i < MI; i++)
#pragma unroll
        for (int j = 0; j < NJ; j++)
#pragma unroll
            for (int q = 0; q < 4; q++) acc[i][j][q] = 0.f;

    const int kchunks = K >> 6;
    const int total = NTERMS * kchunks;

    // stage loader: term/kc select source; 16B chunks with XOR swizzle
    auto load_stage = [&](int s, int term, int kc) {
        const __nv_bfloat16* As = (term == 2) ? A1 : A0;
        const __nv_bfloat16* Bs = (term == 1) ? B1 : B0;
        const uint32_t sA = sb + s * STG;
        const uint32_t sB = sA + ASTG;
#pragma unroll
        for (int i = 0; i < 4; i++) {
            int q = i * 256 + tid;
            int r = q >> 3, c = q & 7;
            cp16(sA + r * 128 + (((c ^ (r & 7)) << 4)),
                 As + (size_t)(bm + r) * lda + kc * 64 + c * 8);
        }
#pragma unroll
        for (int i = 0; i < TN / 32; i++) {
            int q = i * 256 + tid;
            int r = q >> 3, c = q & 7;
            cp16(sB + r * 128 + (((c ^ (r & 7)) << 4)),
                 Bs + (size_t)(bn + r) * ldb + kc * 64 + c * 8);
        }
        CP_COMMIT();
    };

    load_stage(0, 0, 0);
    for (int ch = 0; ch < total; ch++) {
        if (ch + 1 < total) {
            int nt = (ch + 1) / kchunks, nkc = (ch + 1) % kchunks;
            load_stage((ch + 1) & 1, nt, nkc);
            cp_wait<1>();
        } else {
            cp_wait<0>();
        }
        __syncthreads();

        const uint32_t sA = sb + (ch & 1) * STG;
        const uint32_t sB = sA + ASTG;
#pragma unroll
        for (int kk = 0; kk < 4; kk++) {
            uint32_t a[MI][4];
#pragma unroll
            for (int i = 0; i < MI; i++) {
                int r = wm + i * 16 + (lane & 15);
                int c = kk * 2 + (lane >> 4);
                ldm_x4(a[i], sA + r * 128 + (((c ^ (r & 7)) << 4)));
            }
            uint32_t b[NJ][2];
#pragma unroll
            for (int jj = 0; jj < NJ / 2; jj++) {
                int mat = lane >> 3;
                int tile = 2 * jj + (mat >> 1);
                int kh = mat & 1;
                int n = wn + tile * 8 + (lane & 7);
                int c = kk * 2 + kh;
                uint32_t r4[4];
                ldm_x4(r4, sB + n * 128 + (((c ^ (n & 7)) << 4)));
                b[2 * jj][0] = r4[0]; b[2 * jj][1] = r4[1];
                b[2 * jj + 1][0] = r4[2]; b[2 * jj + 1][1] = r4[3];
            }
#pragma unroll
            for (int i = 0; i < MI; i++)
#pragma unroll
                for (int j = 0; j < NJ; j++)
                    mma16816(acc[i][j], a[i], b[j]);
        }
        __syncthreads();
    }
    // pipeline smem now dead; EPI_SIM off-diag reuses it as a 128x128 fp32 tile
    float* sT = reinterpret_cast<float*>(smem);

    // -------- epilogue -------------------------------------------------------
    const int g4 = lane >> 2, t4 = lane & 3;
    float part = 0.f;
#pragma unroll
    for (int i = 0; i < MI; i++) {
#pragma unroll
        for (int p = 0; p < 2; p++) {
            const int m = bm + wm + i * 16 + g4 + p * 8;
            float dl = 1.f;
            int li = 0;
            if (EPI == EPI_SIM) li = g_lab[m];
            else dl = g_dinv[m];
#pragma unroll
            for (int j = 0; j < NJ; j++) {
                const int n = bn + wn + j * 8 + t4 * 2;
                const float v0 = acc[i][j][2 * p + 0];
                const float v1 = acc[i][j][2 * p + 1];
                if (EPI == EPI_SIM) {
                    *reinterpret_cast<float2*>(g_sim + (size_t)m * NNODE + n) =
                        make_float2(v0, v1);
                    const float wgt = diag ? 1.f : 2.f;   // mirror counts twice
                    if (g_lab[n] != li)     part += wgt * v0;
                    if (g_lab[n + 1] != li) part += wgt * v1;
                    if (!diag) {            // stage transpose: sT[n_loc][m_loc]
                        const int nl = wn + j * 8 + t4 * 2;
                        const int ml = wm + i * 16 + g4 + p * 8;
                        const int swz = ((nl >> 1) & 3) << 3;
                        sT[nl * 128 + (ml ^ swz)] = v0;
                        sT[(nl + 1) * 128 + (ml ^ swz)] = v1;
                    }
                } else if (EPI == EPI_XW1T || EPI == EPI_HW2T) {
                    float s0 = dl * v0, s1 = dl * v1;
                    __nv_bfloat16 h0 = __float2bfloat16(s0);
                    __nv_bfloat16 h1 = __float2bfloat16(s1);
                    oh[(size_t)n * NNODE + m] = h0;
                    ol[(size_t)n * NNODE + m] = __float2bfloat16(s0 - __bfloat162float(h0));
                    oh[(size_t)(n + 1) * NNODE + m] = h1;
                    ol[(size_t)(n + 1) * NNODE + m] = __float2bfloat16(s1 - __bfloat162float(h1));
                } else if (EPI == EPI_H) {
                    float s0 = fmaxf(dl * v0 + bias[n], 0.f);
                    float s1 = fmaxf(dl * v1 + bias[n + 1], 0.f);
                    __nv_bfloat16 h0 = __float2bfloat16(s0);
                    __nv_bfloat16 h1 = __float2bfloat16(s1);
                    *reinterpret_cast<__nv_bfloat162*>(oh + (size_t)m * HDIM + n) =
                        __nv_bfloat162(h0, h1);
                    *reinterpret_cast<__nv_bfloat162*>(ol + (size_t)m * HDIM + n) =
                        __nv_bfloat162(__float2bfloat16(s0 - __bfloat162float(h0)),
                                       __float2bfloat16(s1 - __bfloat162float(h1)));
                } else { // EPI_G
                    *reinterpret_cast<float2*>(fout + (size_t)m * OPAD + n) =
                        make_float2(dl * v0 + bias[n], dl * v1 + bias[n + 1]);
                }
            }
        }
    }
    if (EPI == EPI_SIM) {
        if (!diag) {   // coalesced mirror write of transposed tile
            __syncthreads();
            for (int q = tid; q < 128 * 128; q += 256) {
                const int nl = q >> 7, ml = q & 127;
                const int swz = ((nl >> 1) & 3) << 3;
                g_sim[(size_t)(bn + nl) * NNODE + bm + ml] = sT[nl * 128 + (ml ^ swz)];
            }
        }
        s_red[tid] = part;
        __syncthreads();
        for (int off = 128; off > 0; off >>= 1) {
            if (tid < off) s_red[tid] += s_red[tid + off];
            __syncthreads();
        }
        if (tid == 0) atomicAdd(&g_s, (double)s_red[0]);
    }
}

// ---------------- labels: detect int32 vs int64, normalize, exact pair count --
__global__ void lab_k(const int* __restrict__ p) {
    __shared__ int sh[256];
    __shared__ int so[256];
    int o = 0;
    for (int i = threadIdx.x; i < NNODE / 2; i += 256) o |= p[2 * i + 1];
    so[threadIdx.x] = o;
    __syncthreads();
    for (int off = 128; off > 0; off >>= 1) {
        if (threadIdx.x < off) so[threadIdx.x] |= so[threadIdx.x + off];
        __syncthreads();
    }
    const bool is32 = (so[0] != 0);
    int n1 = 0;
    for (int i = threadIdx.x; i < NNODE; i += 256) {
        int v = is32 ? p[i] : p[2 * i];
        g_lab[i] = v;
        n1 += (v != 0) ? 1 : 0;
    }
    sh[threadIdx.x] = n1;
    __syncthreads();
    for (int off = 128; off > 0; off >>= 1) {
        if (threadIdx.x < off) sh[threadIdx.x] += sh[threadIdx.x + off];
        __syncthreads();
    }
    if (threadIdx.x == 0) {
        unsigned long long c1 = (unsigned long long)sh[0];
        g_cnt = 2ULL * c1 * (unsigned long long)(NNODE - c1);
        g_s = 0.0;
        g_ncand = 0;
    }
}

// ---------------- split x into bf16 hi/lo -------------------------------------
__global__ void split_x_k(const float* __restrict__ x) {
    size_t tot = (size_t)NNODE * CDIM;
    for (size_t i = (size_t)blockIdx.x * blockDim.x + threadIdx.x; i < tot;
         i += (size_t)gridDim.x * blockDim.x) {
        float v = x[i];
        __nv_bfloat16 h = __float2bfloat16(v);
        g_xh[i] = h;
        g_xl[i] = __float2bfloat16(v - __bfloat162float(h));
    }
}

// ---------------- weights: transpose + split + pad ----------------------------
__global__ void prep_w_k(const float* __restrict__ W1, const float* __restrict__ W2,
                         const float* __restrict__ b2) {
    size_t idx = (size_t)blockIdx.x * blockDim.x + threadIdx.x;
    size_t stride = (size_t)gridDim.x * blockDim.x;
    if (idx < OPAD) g_b2p[idx] = (idx < ODIM) ? b2[idx] : 0.f;
    size_t t1 = (size_t)HDIM * CDIM;
    for (size_t t = idx; t < t1; t += stride) {
        int n = (int)(t / CDIM), k = (int)(t % CDIM);
        float v = W1[(size_t)k * HDIM + n];
        __nv_bfloat16 h = __float2bfloat16(v);
        g_w1th[t] = h;
        g_w1tl[t] = __float2bfloat16(v - __bfloat162float(h));
    }
    size_t t2 = (size_t)OPAD * HDIM;
    for (size_t t = idx; t < t2; t += stride) {
        int n = (int)(t / HDIM), k = (int)(t % HDIM);
        float v = (n < ODIM) ? W2[(size_t)k * ODIM + n] : 0.f;
        __nv_bfloat16 h = __float2bfloat16(v);
        g_w2th[t] = h;
        g_w2tl[t] = __float2bfloat16(v - __bfloat162float(h));
    }
}

__global__ void thr_final_k() {
    g_thr = (g_cnt > 0ULL) ? (float)(g_s / (double)g_cnt) : 0.f;
}

// ---------------- fixup: collect borderline same-label entries (i<j only) ----
__global__ void collect_k() {
    const float thr = g_thr;
    size_t tot = (size_t)NNODE * NNODE;
    for (size_t idx = (size_t)blockIdx.x * blockDim.x + threadIdx.x; idx < tot;
         idx += (size_t)gridDim.x * blockDim.x) {
        int i = (int)(idx >> 12), j = (int)(idx & (NNODE - 1));
        if (i < j && g_lab[i] == g_lab[j]) {
            float s = g_sim[idx];
            if (fabsf(s - thr) < 2e-3f) {
                int pos = atomicAdd(&g_ncand, 1);
                if (pos < CAND_CAP) g_cand[pos] = make_int2(i, j);
            }
        }
    }
}

// ---------------- fixup: exact fp32 dot for borderline entries (writes both) --
__global__ void fix_k(const float* __restrict__ x) {
    __shared__ float sh[256];
    int nc = g_ncand;
    if (nc > CAND_CAP) nc = CAND_CAP;
    for (int cid = blockIdx.x; cid < nc; cid += gridDim.x) {
        int2 c = g_cand[cid];
        const float* xi = x + (size_t)c.x * CDIM;
        const float* xj = x + (size_t)c.y * CDIM;
        float s = 0.f;
        for (int k = threadIdx.x; k < CDIM; k += 256) s += xi[k] * xj[k];
        sh[threadIdx.x] = s;
        __syncthreads();
        for (int off = 128; off > 0; off >>= 1) {
            if (threadIdx.x < off) sh[threadIdx.x] += sh[threadIdx.x + off];
            __syncthreads();
        }
        if (threadIdx.x == 0) {
            g_sim[(size_t)c.x * NNODE + c.y] = sh[0];
            g_sim[(size_t)c.y * NNODE + c.x] = sh[0];
        }
        __syncthreads();
    }
}

// ---------------- mask: sim -> a01 bf16 (A+I), loss_mask, dinv ----------------
__global__ void mask_deg_k(float* __restrict__ loss_out, int write_loss) {
    const int i = blockIdx.x;
    const int li = g_lab[i];
    const float thr = g_thr;
    int deg = 0;
    const size_t row = (size_t)i * NNODE;
    for (int j0 = threadIdx.x * 4; j0 < NNODE; j0 += blockDim.x * 4) {
        float4 sv = *reinterpret_cast<const float4*>(g_sim + row + j0);
        float a[4], lm[4];
#pragma unroll
        for (int q = 0; q < 4; q++) {
            int j = j0 + q;
            float s = (q == 0) ? sv.x : (q == 1) ? sv.y : (q == 2) ? sv.z : sv.w;
            bool same = (g_lab[j] == li) && (j != i);
            bool edge = same && (s <= thr);
            deg += edge ? 1 : 0;
            a[q] = (edge || (j == i)) ? 1.f : 0.f;
            lm[q] = (edge && (i < j)) ? 1.f : 0.f;
        }
        __nv_bfloat162* ap = reinterpret_cast<__nv_bfloat162*>(g_a01 + row + j0);
        ap[0] = __floats2bfloat162_rn(a[0], a[1]);
        ap[1] = __floats2bfloat162_rn(a[2], a[3]);
        if (write_loss)
            *reinterpret_cast<float4*>(loss_out + row + j0) = make_float4(lm[0], lm[1], lm[2], lm[3]);
    }
    __shared__ int sh[256];
    sh[threadIdx.x] = deg;
    __syncthreads();
    for (int off = 128; off > 0; off >>= 1) {
        if (threadIdx.x < off) sh[threadIdx.x] += sh[threadIdx.x + off];
        __syncthreads();
    }
    if (threadIdx.x == 0) g_dinv[i] = rsqrtf((float)(sh[0] + 1));
}

// ---------------- f_g writer + x copy -----------------------------------------
__global__ void fg_write_k(const float* __restrict__ x, float* __restrict__ fg,
                           float* __restrict__ xout) {
    const int FDIM = CDIM + ODIM;
    size_t tot = (size_t)NNODE * FDIM;
    for (size_t idx = (size_t)blockIdx.x * blockDim.x + threadIdx.x; idx < tot;
         idx += (size_t)gridDim.x * blockDim.x) {
        int i = (int)(idx / FDIM), c = (int)(idx % FDIM);
        fg[idx] = (c < CDIM) ? x[(size_t)i * CDIM + c]
                             : g_g[(size_t)i * OPAD + (c - CDIM)];
    }
    size_t totx = (size_t)NNODE * CDIM;
    for (size_t idx = (size_t)blockIdx.x * blockDim.x + threadIdx.x; idx < totx;
         idx += (size_t)gridDim.x * blockDim.x)
        xout[idx] = x[idx];
}

// ---------------- final GEMV: out = [x, g] @ fcW + fcb ------------------------
__global__ void out_gemv_k(const float* __restrict__ x, const float* __restrict__ fcW,
                           const float* __restrict__ fcb, float* __restrict__ out) {
    const int i = blockIdx.x;
    float s = 0.f;
    for (int c = threadIdx.x; c < CDIM; c += blockDim.x)
        s += x[(size_t)i * CDIM + c] * fcW[c];
    for (int o = threadIdx.x; o < ODIM; o += blockDim.x)
        s += g_g[(size_t)i * OPAD + o] * fcW[CDIM + o];
    __shared__ float sh[256];
    sh[threadIdx.x] = s;
    __syncthreads();
    for (int off = 128; off > 0; off >>= 1) {
        if (threadIdx.x < off) sh[threadIdx.x] += sh[threadIdx.x + off];
        __syncthreads();
    }
    if (threadIdx.x == 0) out[i] = sh[0] + fcb[0];
}

// ---------------- launch ------------------------------------------------------
extern "C" void kernel_launch(void* const* d_in, const int* in_sizes, int n_in,
                              void* d_out, int out_size) {
    const float* x   = (const float*)d_in[0];
    const int*   lab = (const int*)d_in[1];
    const float* W1  = (const float*)d_in[2];
    const float* b1  = (const float*)d_in[3];
    const float* W2  = (const float*)d_in[4];
    const float* b2  = (const float*)d_in[5];
    const float* fcW = (const float*)d_in[6];
    const float* fcb = (const float*)d_in[7];
    (void)in_sizes; (void)n_in;

    const size_t SZ_OUT = NNODE;
    const size_t SZ_FG  = (size_t)NNODE * (CDIM + ODIM);
    const size_t SZ_LM  = (size_t)NNODE * NNODE;
    const size_t SZ_X   = (size_t)NNODE * CDIM;
    const bool full = ((size_t)out_size >= SZ_OUT + SZ_FG + SZ_LM + SZ_X);

    float* o_out = (float*)d_out;
    float* o_fg  = o_out + SZ_OUT;
    float* o_lm  = o_fg + SZ_FG;
    float* o_x   = o_lm + SZ_LM;

    __nv_bfloat16 *xh, *xl, *w1th, *w1tl, *w2th, *w2tl, *xw1th, *xw1tl, *hh, *hl, *hw2th, *hw2tl, *a01;
    float *gp, *b2pp;
    cudaGetSymbolAddress((void**)&xh, g_xh);       cudaGetSymbolAddress((void**)&xl, g_xl);
    cudaGetSymbolAddress((void**)&w1th, g_w1th);   cudaGetSymbolAddress((void**)&w1tl, g_w1tl);
    cudaGetSymbolAddress((void**)&w2th, g_w2th);   cudaGetSymbolAddress((void**)&w2tl, g_w2tl);
    cudaGetSymbolAddress((void**)&xw1th, g_xw1th); cudaGetSymbolAddress((void**)&xw1tl, g_xw1tl);
    cudaGetSymbolAddress((void**)&hh, g_hh);       cudaGetSymbolAddress((void**)&hl, g_hl);
    cudaGetSymbolAddress((void**)&hw2th, g_hw2th); cudaGetSymbolAddress((void**)&hw2tl, g_hw2tl);
    cudaGetSymbolAddress((void**)&a01, g_a01);
    cudaGetSymbolAddress((void**)&gp, g_g);
    cudaGetSymbolAddress((void**)&b2pp, g_b2p);

    const int SM128 = 2 * (128 * 128 + 128 * 128);  // 65536 (also fits 128x128 fp32 mirror tile)
    const int SM64  = 2 * (128 * 128 + 64 * 128);   // 49152
    cudaFuncSetAttribute(mma_gemm_k<128, 3, EPI_SIM>,  cudaFuncAttributeMaxDynamicSharedMemorySize, SM128);
    cudaFuncSetAttribute(mma_gemm_k<128, 3, EPI_XW1T>, cudaFuncAttributeMaxDynamicSharedMemorySize, SM128);
    cudaFuncSetAttribute(mma_gemm_k<128, 2, EPI_H>,    cudaFuncAttributeMaxDynamicSharedMemorySize, SM128);
    cudaFuncSetAttribute(mma_gemm_k<64, 3, EPI_HW2T>,  cudaFuncAttributeMaxDynamicSharedMemorySize, SM64);
    cudaFuncSetAttribute(mma_gemm_k<64, 2, EPI_G>,     cudaFuncAttributeMaxDynamicSharedMemorySize, SM64);

    // 0. labels + splits + weight prep
    lab_k<<<1, 256>>>(lab);
    split_x_k<<<512, 256>>>(x);
    prep_w_k<<<256, 256>>>(W1, W2, b2);

    // 1. sim = x @ x^T  (3-term bf16 split, SYMMETRIC: 528 upper-tri blocks)
    mma_gemm_k<128, 3, EPI_SIM><<<528, 256, SM128>>>(
        xh, xl, xh, xl, CDIM, CDIM, CDIM, nullptr, nullptr, nullptr, nullptr);

    // 2. threshold, then exact-fp32 fixup of borderline entries
    thr_final_k<<<1, 1>>>();
    collect_k<<<4096, 256>>>();
    fix_k<<<1024, 256>>>(x);

    // 3. mask: sim -> a01 (A+I, exact bf16), loss_mask, dinv
    mask_deg_k<<<NNODE, 256>>>(full ? o_lm : nullptr, full ? 1 : 0);

    // 4. xw1 = x @ W1; write (dinv_j * xw1)^T hi/lo   [512 x 4096]
    mma_gemm_k<128, 3, EPI_XW1T><<<dim3(HDIM / 128, 32), 256, SM128>>>(
        xh, xl, w1th, w1tl, CDIM, CDIM, CDIM, nullptr, xw1th, xw1tl, nullptr);

    // 5. h = relu(dinv_i * (a01 @ xw1t) + b1); write h hi/lo  [4096 x 512]
    mma_gemm_k<128, 2, EPI_H><<<dim3(HDIM / 128, 32), 256, SM128>>>(
        a01, a01, xw1th, xw1tl, NNODE, NNODE, NNODE, nullptr, hh, hl, b1);

    // 6. hw2 = h @ W2p; write (dinv_j * hw2)^T hi/lo  [64 x 4096]
    mma_gemm_k<64, 3, EPI_HW2T><<<dim3(1, 32), 256, SM64>>>(
        hh, hl, w2th, w2tl, HDIM, HDIM, HDIM, nullptr, hw2th, hw2tl, nullptr);

    // 7. g = dinv_i * (a01 @ hw2t) + b2p   [4096 x 64] fp32
    mma_gemm_k<64, 2, EPI_G><<<dim3(1, 32), 256, SM64>>>(
        a01, a01, hw2th, hw2tl, NNODE, NNODE, NNODE, gp, nullptr, nullptr, b2pp);

    // 8. outputs
    if (full) fg_write_k<<<4096, 256>>>(x, o_fg, o_x);
    out_gemv_k<<<NNODE, 256>>>(x, fcW, fcb, o_out);
}

// round 6
// speedup vs baseline: 8.1203x; 1.6368x over previous
#include <cuda_runtime.h>
#include <cuda_bf16.h>
#include <cuda_fp16.h>
#include <cstdint>

#define NNODE 4096
#define CDIM  768
#define HDIM  512
#define ODIM  50
#define OPAD  64

#define EPI_SIM  0
#define EPI_XW1T 1
#define EPI_H    2
#define EPI_HW2T 3
#define EPI_G    4

#define CAND_CAP 65536
#define FIXWIN 0.12f

// ---------------- device scratch (static: no allocations allowed) -------------
__device__ __align__(16) float         g_sim[(size_t)NNODE * NNODE];
__device__ __align__(16) __nv_bfloat16 g_a01[(size_t)NNODE * NNODE];
__device__ __align__(16) __half        g_xf16[(size_t)NNODE * CDIM];
__device__ __align__(16) __nv_bfloat16 g_xbh[(size_t)NNODE * CDIM];
__device__ __align__(16) __nv_bfloat16 g_w1th[(size_t)HDIM * CDIM];
__device__ __align__(16) __nv_bfloat16 g_w2th[(size_t)OPAD * HDIM];
__device__ __align__(16) __nv_bfloat16 g_xw1th[(size_t)HDIM * NNODE];
__device__ __align__(16) __nv_bfloat16 g_hh[(size_t)NNODE * HDIM];
__device__ __align__(16) __nv_bfloat16 g_hw2th[(size_t)OPAD * NNODE];
__device__ __align__(16) float g_g[(size_t)NNODE * OPAD];
__device__ float g_b2p[OPAD];
__device__ float g_dinv[NNODE];
__device__ int   g_lab[NNODE];
__device__ double g_s0d[CDIM], g_s1d[CDIM];
__device__ unsigned long long g_cnt;
__device__ float g_thr;
__device__ int   g_ncand;
__device__ int2  g_cand[CAND_CAP];

// ---------------- PTX helpers (all sm_80-compatible) ---------------------------
__device__ __forceinline__ uint32_t smem_u32(const void* p) {
    uint32_t a;
    asm("{ .reg .u64 t; cvta.to.shared.u64 t, %1; cvt.u32.u64 %0, t; }" : "=r"(a) : "l"(p));
    return a;
}
__device__ __forceinline__ void cp16(uint32_t d, const void* g) {
    asm volatile("cp.async.cg.shared.global [%0], [%1], 16;" :: "r"(d), "l"(g));
}
#define CP_COMMIT() asm volatile("cp.async.commit_group;" ::: "memory")
template<int N> __device__ __forceinline__ void cp_wait() {
    asm volatile("cp.async.wait_group %0;" :: "n"(N) : "memory");
}
__device__ __forceinline__ void ldm_x4(uint32_t* r, uint32_t addr) {
    asm volatile("ldmatrix.sync.aligned.m8n8.x4.shared.b16 {%0,%1,%2,%3}, [%4];"
        : "=r"(r[0]), "=r"(r[1]), "=r"(r[2]), "=r"(r[3]) : "r"(addr));
}
__device__ __forceinline__ void mma_bf16(float* c, const uint32_t* a, const uint32_t* b) {
    asm volatile(
        "mma.sync.aligned.m16n8k16.row.col.f32.bf16.bf16.f32 "
        "{%0,%1,%2,%3}, {%4,%5,%6,%7}, {%8,%9}, {%0,%1,%2,%3};"
        : "+f"(c[0]), "+f"(c[1]), "+f"(c[2]), "+f"(c[3])
        : "r"(a[0]), "r"(a[1]), "r"(a[2]), "r"(a[3]), "r"(b[0]), "r"(b[1]));
}
__device__ __forceinline__ void mma_fp16(float* c, const uint32_t* a, const uint32_t* b) {
    asm volatile(
        "mma.sync.aligned.m16n8k16.row.col.f32.f16.f16.f32 "
        "{%0,%1,%2,%3}, {%4,%5,%6,%7}, {%8,%9}, {%0,%1,%2,%3};"
        : "+f"(c[0]), "+f"(c[1]), "+f"(c[2]), "+f"(c[3])
        : "r"(a[0]), "r"(a[1]), "r"(a[2]), "r"(a[3]), "r"(b[0]), "r"(b[1]));
}

// ---------------- mma.sync GEMM: D[M,N] = A[M,K] * B[N,K]^T (single term) -----
// A,B row-major K-major 16-bit. BM=128, BK=64, 2-stage cp.async pipeline,
// XOR swizzle (conflict-free ldmatrix). 8 warps.
// EPI_SIM: symmetric — grid enumerates upper-triangle blocks (bi<=bj);
// off-diagonal blocks mirrored to lower triangle via smem transpose.
template<int TN, bool FP16, int EPI>
__global__ void __launch_bounds__(256)
mma_gemm_k(const __nv_bfloat16* __restrict__ A0, const __nv_bfloat16* __restrict__ B0,
           int K, int lda, int ldb,
           float* __restrict__ fout, __nv_bfloat16* __restrict__ oh,
           const float* __restrict__ bias)
{
    constexpr int WN = 32;
    constexpr int WM = (TN == 128) ? 64 : 32;
    constexpr int WX = TN / WN;
    constexpr int MI = WM / 16;
    constexpr int NJ = WN / 8;
    constexpr int ASTG = 128 * 128;
    constexpr int BSTG = TN * 128;
    constexpr int STG = ASTG + BSTG;

    extern __shared__ char smem[];
    const uint32_t sb = smem_u32(smem);
    const int tid = threadIdx.x;
    const int w = tid >> 5, lane = tid & 31;
    const int wm = (w / WX) * WM, wn = (w % WX) * WN;

    int bm, bn;
    bool diag = true;
    if (EPI == EPI_SIM) {
        int idx = blockIdx.x;
        int bi = 0;
        while (idx >= 32 - bi) { idx -= 32 - bi; bi++; }
        int bj = bi + idx;
        bm = bi * 128;
        bn = bj * 128;
        diag = (bi == bj);
    } else {
        bm = blockIdx.y * 128;
        bn = blockIdx.x * TN;
    }

    float acc[MI][NJ][4];
#pragma unroll
    for (int i = 0; i < MI; i++)
#pragma unroll
        for (int j = 0; j < NJ; j++)
#pragma unroll
            for (int q = 0; q < 4; q++) acc[i][j][q] = 0.f;

    const int kchunks = K >> 6;

    auto load_stage = [&](int s, int kc) {
        const uint32_t sA = sb + s * STG;
        const uint32_t sB = sA + ASTG;
#pragma unroll
        for (int i = 0; i < 4; i++) {
            int q = i * 256 + tid;
            int r = q >> 3, c = q & 7;
            cp16(sA + r * 128 + (((c ^ (r & 7)) << 4)),
                 A0 + (size_t)(bm + r) * lda + kc * 64 + c * 8);
        }
#pragma unroll
        for (int i = 0; i < TN / 32; i++) {
            int q = i * 256 + tid;
            int r = q >> 3, c = q & 7;
            cp16(sB + r * 128 + (((c ^ (r & 7)) << 4)),
                 B0 + (size_t)(bn + r) * ldb + kc * 64 + c * 8);
        }
        CP_COMMIT();
    };

    load_stage(0, 0);
    for (int ch = 0; ch < kchunks; ch++) {
        if (ch + 1 < kchunks) {
            load_stage((ch + 1) & 1, ch + 1);
            cp_wait<1>();
        } else {
            cp_wait<0>();
        }
        __syncthreads();

        const uint32_t sA = sb + (ch & 1) * STG;
        const uint32_t sB = sA + ASTG;
#pragma unroll
        for (int kk = 0; kk < 4; kk++) {
            uint32_t a[MI][4];
#pragma unroll
            for (int i = 0; i < MI; i++) {
                int r = wm + i * 16 + (lane & 15);
                int c = kk * 2 + (lane >> 4);
                ldm_x4(a[i], sA + r * 128 + (((c ^ (r & 7)) << 4)));
            }
            uint32_t b[NJ][2];
#pragma unroll
            for (int jj = 0; jj < NJ / 2; jj++) {
                int mat = lane >> 3;
                int tile = 2 * jj + (mat >> 1);
                int kh = mat & 1;
                int n = wn + tile * 8 + (lane & 7);
                int c = kk * 2 + kh;
                uint32_t r4[4];
                ldm_x4(r4, sB + n * 128 + (((c ^ (n & 7)) << 4)));
                b[2 * jj][0] = r4[0]; b[2 * jj][1] = r4[1];
                b[2 * jj + 1][0] = r4[2]; b[2 * jj + 1][1] = r4[3];
            }
#pragma unroll
            for (int i = 0; i < MI; i++)
#pragma unroll
                for (int j = 0; j < NJ; j++) {
                    if (FP16) mma_fp16(acc[i][j], a[i], b[j]);
                    else      mma_bf16(acc[i][j], a[i], b[j]);
                }
        }
        __syncthreads();
    }
    // pipeline smem dead; EPI_SIM off-diag reuses it as a 128x128 fp32 tile
    float* sT = reinterpret_cast<float*>(smem);

    // -------- epilogue -------------------------------------------------------
    const int g4 = lane >> 2, t4 = lane & 3;
#pragma unroll
    for (int i = 0; i < MI; i++) {
#pragma unroll
        for (int p = 0; p < 2; p++) {
            const int m = bm + wm + i * 16 + g4 + p * 8;
            float dl = 1.f;
            if (EPI != EPI_SIM) dl = g_dinv[m];
#pragma unroll
            for (int j = 0; j < NJ; j++) {
                const int n = bn + wn + j * 8 + t4 * 2;
                const float v0 = acc[i][j][2 * p + 0];
                const float v1 = acc[i][j][2 * p + 1];
                if (EPI == EPI_SIM) {
                    *reinterpret_cast<float2*>(g_sim + (size_t)m * NNODE + n) =
                        make_float2(v0, v1);
                    if (!diag) {
                        const int nl = wn + j * 8 + t4 * 2;
                        const int ml = wm + i * 16 + g4 + p * 8;
                        const int swz = ((nl >> 1) & 3) << 3;
                        sT[nl * 128 + (ml ^ swz)] = v0;
                        sT[(nl + 1) * 128 + (ml ^ swz)] = v1;
                    }
                } else if (EPI == EPI_XW1T || EPI == EPI_HW2T) {
                    oh[(size_t)n * NNODE + m] = __float2bfloat16(dl * v0);
                    oh[(size_t)(n + 1) * NNODE + m] = __float2bfloat16(dl * v1);
                } else if (EPI == EPI_H) {
                    float s0 = fmaxf(dl * v0 + bias[n], 0.f);
                    float s1 = fmaxf(dl * v1 + bias[n + 1], 0.f);
                    *reinterpret_cast<__nv_bfloat162*>(oh + (size_t)m * HDIM + n) =
                        __nv_bfloat162(__float2bfloat16(s0), __float2bfloat16(s1));
                } else { // EPI_G
                    *reinterpret_cast<float2*>(fout + (size_t)m * OPAD + n) =
                        make_float2(dl * v0 + bias[n], dl * v1 + bias[n + 1]);
                }
            }
        }
    }
    if (EPI == EPI_SIM && !diag) {
        __syncthreads();
        for (int q = tid; q < 128 * 128; q += 256) {
            const int nl = q >> 7, ml = q & 127;
            const int swz = ((nl >> 1) & 3) << 3;
            g_sim[(size_t)(bn + nl) * NNODE + bm + ml] = sT[nl * 128 + (ml ^ swz)];
        }
    }
}

// ---------------- labels: detect int32 vs int64, normalize, cnt, zero sums ----
__global__ void lab_k(const int* __restrict__ p) {
    __shared__ int sh[256];
    __shared__ int so[256];
    for (int i = threadIdx.x; i < CDIM; i += 256) { g_s0d[i] = 0.0; g_s1d[i] = 0.0; }
    int o = 0;
    for (int i = threadIdx.x; i < NNODE / 2; i += 256) o |= p[2 * i + 1];
    so[threadIdx.x] = o;
    __syncthreads();
    for (int off = 128; off > 0; off >>= 1) {
        if (threadIdx.x < off) so[threadIdx.x] |= so[threadIdx.x + off];
        __syncthreads();
    }
    const bool is32 = (so[0] != 0);
    int n1 = 0;
    for (int i = threadIdx.x; i < NNODE; i += 256) {
        int v = is32 ? p[i] : p[2 * i];
        g_lab[i] = v;
        n1 += (v != 0) ? 1 : 0;
    }
    sh[threadIdx.x] = n1;
    __syncthreads();
    for (int off = 128; off > 0; off >>= 1) {
        if (threadIdx.x < off) sh[threadIdx.x] += sh[threadIdx.x + off];
        __syncthreads();
    }
    if (threadIdx.x == 0) {
        unsigned long long c1 = (unsigned long long)sh[0];
        g_cnt = 2ULL * c1 * (unsigned long long)(NNODE - c1);
        g_ncand = 0;
    }
}

// ---------------- per-label column sums of x (exact threshold) ----------------
__global__ void lab_sum_k(const float* __restrict__ x) {
    const int b = blockIdx.x;           // 256 blocks x 16 rows
    const int t = threadIdx.x;          // 256 threads; 3 cols each
    float a0[3] = {0.f, 0.f, 0.f}, a1[3] = {0.f, 0.f, 0.f};
    for (int r = b * 16; r < b * 16 + 16; r++) {
        const float* row = x + (size_t)r * CDIM;
        const bool l1 = (g_lab[r] != 0);
#pragma unroll
        for (int q = 0; q < 3; q++) {
            float v = row[t + q * 256];
            if (l1) a1[q] += v; else a0[q] += v;
        }
    }
#pragma unroll
    for (int q = 0; q < 3; q++) {
        atomicAdd(&g_s0d[t + q * 256], (double)a0[q]);
        atomicAdd(&g_s1d[t + q * 256], (double)a1[q]);
    }
}

// thr = 2 * s0 . s1 / cnt   (exact collapse of the cross-label sim sum)
__global__ void thr_dot_k() {
    __shared__ double sh[256];
    double s = 0.0;
    for (int c = threadIdx.x; c < CDIM; c += 256) s += g_s0d[c] * g_s1d[c];
    sh[threadIdx.x] = s;
    __syncthreads();
    for (int off = 128; off > 0; off >>= 1) {
        if (threadIdx.x < off) sh[threadIdx.x] += sh[threadIdx.x + off];
        __syncthreads();
    }
    if (threadIdx.x == 0)
        g_thr = (g_cnt > 0ULL) ? (float)(2.0 * sh[0] / (double)g_cnt) : 0.f;
}

// ---------------- split x into fp16 (sim) + bf16 (xw1) ------------------------
__global__ void split_x_k(const float* __restrict__ x) {
    size_t tot = (size_t)NNODE * CDIM;
    for (size_t i = (size_t)blockIdx.x * blockDim.x + threadIdx.x; i < tot;
         i += (size_t)gridDim.x * blockDim.x) {
        float v = x[i];
        g_xf16[i] = __float2half(v);
        g_xbh[i] = __float2bfloat16(v);
    }
}

// ---------------- weights: transpose + bf16 + pad -----------------------------
__global__ void prep_w_k(const float* __restrict__ W1, const float* __restrict__ W2,
                         const float* __restrict__ b2) {
    size_t idx = (size_t)blockIdx.x * blockDim.x + threadIdx.x;
    size_t stride = (size_t)gridDim.x * blockDim.x;
    if (idx < OPAD) g_b2p[idx] = (idx < ODIM) ? b2[idx] : 0.f;
    size_t t1 = (size_t)HDIM * CDIM;
    for (size_t t = idx; t < t1; t += stride) {
        int n = (int)(t / CDIM), k = (int)(t % CDIM);
        g_w1th[t] = __float2bfloat16(W1[(size_t)k * HDIM + n]);
    }
    size_t t2 = (size_t)OPAD * HDIM;
    for (size_t t = idx; t < t2; t += stride) {
        int n = (int)(t / HDIM), k = (int)(t % HDIM);
        g_w2th[t] = __float2bfloat16((n < ODIM) ? W2[(size_t)k * ODIM + n] : 0.f);
    }
}

// ---------------- fixup: collect borderline same-label entries (i<j) ----------
__global__ void collect_k() {
    const float thr = g_thr;
    size_t tot = (size_t)NNODE * NNODE;
    for (size_t idx = (size_t)blockIdx.x * blockDim.x + threadIdx.x; idx < tot;
         idx += (size_t)gridDim.x * blockDim.x) {
        int i = (int)(idx >> 12), j = (int)(idx & (NNODE - 1));
        if (i < j && g_lab[i] == g_lab[j]) {
            float s = g_sim[idx];
            if (fabsf(s - thr) < FIXWIN) {
                int pos = atomicAdd(&g_ncand, 1);
                if (pos < CAND_CAP) g_cand[pos] = make_int2(i, j);
            }
        }
    }
}

// ---------------- fixup: exact fp32 dot, warp per candidate, writes both -----
__global__ void fix_k(const float* __restrict__ x) {
    int nc = g_ncand;
    if (nc > CAND_CAP) nc = CAND_CAP;
    const int gw = (blockIdx.x * blockDim.x + threadIdx.x) >> 5;
    const int lane = threadIdx.x & 31;
    const int nw = (gridDim.x * blockDim.x) >> 5;
    for (int cid = gw; cid < nc; cid += nw) {
        int2 c = g_cand[cid];
        const float4* xi = reinterpret_cast<const float4*>(x + (size_t)c.x * CDIM);
        const float4* xj = reinterpret_cast<const float4*>(x + (size_t)c.y * CDIM);
        float s = 0.f;
        for (int k = lane; k < CDIM / 4; k += 32) {
            float4 a = xi[k], b = xj[k];
            s += a.x * b.x + a.y * b.y + a.z * b.z + a.w * b.w;
        }
#pragma unroll
        for (int o = 16; o > 0; o >>= 1) s += __shfl_xor_sync(0xFFFFFFFFu, s, o);
        if (lane == 0) {
            g_sim[(size_t)c.x * NNODE + c.y] = s;
            g_sim[(size_t)c.y * NNODE + c.x] = s;
        }
    }
}

// ---------------- mask: sim -> a01 bf16 (A+I), loss_mask, dinv ----------------
__global__ void mask_deg_k(float* __restrict__ loss_out, int write_loss) {
    const int i = blockIdx.x;
    const int li = g_lab[i];
    const float thr = g_thr;
    int deg = 0;
    const size_t row = (size_t)i * NNODE;
    for (int j0 = threadIdx.x * 4; j0 < NNODE; j0 += blockDim.x * 4) {
        float4 sv = *reinterpret_cast<const float4*>(g_sim + row + j0);
        float a[4], lm[4];
#pragma unroll
        for (int q = 0; q < 4; q++) {
            int j = j0 + q;
            float s = (q == 0) ? sv.x : (q == 1) ? sv.y : (q == 2) ? sv.z : sv.w;
            bool same = (g_lab[j] == li) && (j != i);
            bool edge = same && (s <= thr);
            deg += edge ? 1 : 0;
            a[q] = (edge || (j == i)) ? 1.f : 0.f;
            lm[q] = (edge && (i < j)) ? 1.f : 0.f;
        }
        __nv_bfloat162* ap = reinterpret_cast<__nv_bfloat162*>(g_a01 + row + j0);
        ap[0] = __floats2bfloat162_rn(a[0], a[1]);
        ap[1] = __floats2bfloat162_rn(a[2], a[3]);
        if (write_loss)
            *reinterpret_cast<float4*>(loss_out + row + j0) = make_float4(lm[0], lm[1], lm[2], lm[3]);
    }
    __shared__ int sh[256];
    sh[threadIdx.x] = deg;
    __syncthreads();
    for (int off = 128; off > 0; off >>= 1) {
        if (threadIdx.x < off) sh[threadIdx.x] += sh[threadIdx.x + off];
        __syncthreads();
    }
    if (threadIdx.x == 0) g_dinv[i] = rsqrtf((float)(sh[0] + 1));
}

// ---------------- f_g writer + x copy -----------------------------------------
__global__ void fg_write_k(const float* __restrict__ x, float* __restrict__ fg,
                           float* __restrict__ xout) {
    const int FDIM = CDIM + ODIM;
    size_t tot = (size_t)NNODE * FDIM;
    for (size_t idx = (size_t)blockIdx.x * blockDim.x + threadIdx.x; idx < tot;
         idx += (size_t)gridDim.x * blockDim.x) {
        int i = (int)(idx / FDIM), c = (int)(idx % FDIM);
        fg[idx] = (c < CDIM) ? x[(size_t)i * CDIM + c]
                             : g_g[(size_t)i * OPAD + (c - CDIM)];
    }
    size_t totx = (size_t)NNODE * CDIM;
    for (size_t idx = (size_t)blockIdx.x * blockDim.x + threadIdx.x; idx < totx;
         idx += (size_t)gridDim.x * blockDim.x)
        xout[idx] = x[idx];
}

// ---------------- final GEMV: out = [x, g] @ fcW + fcb ------------------------
__global__ void out_gemv_k(const float* __restrict__ x, const float* __restrict__ fcW,
                           const float* __restrict__ fcb, float* __restrict__ out) {
    const int i = blockIdx.x;
    float s = 0.f;
    for (int c = threadIdx.x; c < CDIM; c += blockDim.x)
        s += x[(size_t)i * CDIM + c] * fcW[c];
    for (int o = threadIdx.x; o < ODIM; o += blockDim.x)
        s += g_g[(size_t)i * OPAD + o] * fcW[CDIM + o];
    __shared__ float sh[256];
    sh[threadIdx.x] = s;
    __syncthreads();
    for (int off = 128; off > 0; off >>= 1) {
        if (threadIdx.x < off) sh[threadIdx.x] += sh[threadIdx.x + off];
        __syncthreads();
    }
    if (threadIdx.x == 0) out[i] = sh[0] + fcb[0];
}

// ---------------- launch ------------------------------------------------------
extern "C" void kernel_launch(void* const* d_in, const int* in_sizes, int n_in,
                              void* d_out, int out_size) {
    const float* x   = (const float*)d_in[0];
    const int*   lab = (const int*)d_in[1];
    const float* W1  = (const float*)d_in[2];
    const float* b1  = (const float*)d_in[3];
    const float* W2  = (const float*)d_in[4];
    const float* b2  = (const float*)d_in[5];
    const float* fcW = (const float*)d_in[6];
    const float* fcb = (const float*)d_in[7];
    (void)in_sizes; (void)n_in;

    const size_t SZ_OUT = NNODE;
    const size_t SZ_FG  = (size_t)NNODE * (CDIM + ODIM);
    const size_t SZ_LM  = (size_t)NNODE * NNODE;
    const size_t SZ_X   = (size_t)NNODE * CDIM;
    const bool full = ((size_t)out_size >= SZ_OUT + SZ_FG + SZ_LM + SZ_X);

    float* o_out = (float*)d_out;
    float* o_fg  = o_out + SZ_OUT;
    float* o_lm  = o_fg + SZ_FG;
    float* o_x   = o_lm + SZ_LM;

    __nv_bfloat16 *xbh, *w1th, *w2th, *xw1th, *hh, *hw2th, *a01;
    __half* xf16;
    float *gp, *b2pp;
    cudaGetSymbolAddress((void**)&xf16, g_xf16);
    cudaGetSymbolAddress((void**)&xbh, g_xbh);
    cudaGetSymbolAddress((void**)&w1th, g_w1th);
    cudaGetSymbolAddress((void**)&w2th, g_w2th);
    cudaGetSymbolAddress((void**)&xw1th, g_xw1th);
    cudaGetSymbolAddress((void**)&hh, g_hh);
    cudaGetSymbolAddress((void**)&hw2th, g_hw2th);
    cudaGetSymbolAddress((void**)&a01, g_a01);
    cudaGetSymbolAddress((void**)&gp, g_g);
    cudaGetSymbolAddress((void**)&b2pp, g_b2p);

    const int SM128 = 2 * (128 * 128 + 128 * 128);  // 65536 (fits the fp32 mirror tile)
    const int SM64  = 2 * (128 * 128 + 64 * 128);   // 49152
    cudaFuncSetAttribute(mma_gemm_k<128, true,  EPI_SIM>,  cudaFuncAttributeMaxDynamicSharedMemorySize, SM128);
    cudaFuncSetAttribute(mma_gemm_k<128, false, EPI_XW1T>, cudaFuncAttributeMaxDynamicSharedMemorySize, SM128);
    cudaFuncSetAttribute(mma_gemm_k<128, false, EPI_H>,    cudaFuncAttributeMaxDynamicSharedMemorySize, SM128);
    cudaFuncSetAttribute(mma_gemm_k<64, false, EPI_HW2T>,  cudaFuncAttributeMaxDynamicSharedMemorySize, SM64);
    cudaFuncSetAttribute(mma_gemm_k<64, false, EPI_G>,     cudaFuncAttributeMaxDynamicSharedMemorySize, SM64);

    // 0. labels + converts + weight prep + exact threshold
    lab_k<<<1, 256>>>(lab);
    split_x_k<<<512, 256>>>(x);
    prep_w_k<<<256, 256>>>(W1, W2, b2);
    lab_sum_k<<<256, 256>>>(x);
    thr_dot_k<<<1, 256>>>();

    // 1. sim = x @ x^T  (fp16 single-term, SYMMETRIC: 528 upper-tri blocks)
    mma_gemm_k<128, true, EPI_SIM><<<528, 256, SM128>>>(
        (const __nv_bfloat16*)xf16, (const __nv_bfloat16*)xf16,
        CDIM, CDIM, CDIM, nullptr, nullptr, nullptr);

    // 2. exact fp32 fixup of borderline entries (window = 11 sigma of fp16 err)
    collect_k<<<4096, 256>>>();
    fix_k<<<256, 256>>>(x);

    // 3. mask: sim -> a01 (A+I, exact bf16), loss_mask, dinv
    mask_deg_k<<<NNODE, 256>>>(full ? o_lm : nullptr, full ? 1 : 0);

    // 4. xw1 = x @ W1; write (dinv_j * xw1)^T bf16   [512 x 4096]
    mma_gemm_k<128, false, EPI_XW1T><<<dim3(HDIM / 128, 32), 256, SM128>>>(
        xbh, w1th, CDIM, CDIM, CDIM, nullptr, xw1th, nullptr);

    // 5. h = relu(dinv_i * (a01 @ xw1t) + b1) bf16   [4096 x 512]
    mma_gemm_k<128, false, EPI_H><<<dim3(HDIM / 128, 32), 256, SM128>>>(
        a01, xw1th, NNODE, NNODE, NNODE, nullptr, hh, b1);

    // 6. hw2 = h @ W2p; write (dinv_j * hw2)^T bf16  [64 x 4096]
    mma_gemm_k<64, false, EPI_HW2T><<<dim3(1, 32), 256, SM64>>>(
        hh, w2th, HDIM, HDIM, HDIM, nullptr, hw2th, nullptr);

    // 7. g = dinv_i * (a01 @ hw2t) + b2p   [4096 x 64] fp32
    mma_gemm_k<64, false, EPI_G><<<dim3(1, 32), 256, SM64>>>(
        a01, hw2th, NNODE, NNODE, NNODE, gp, nullptr, b2pp);

    // 8. outputs
    if (full) fg_write_k<<<4096, 256>>>(x, o_fg, o_x);
    out_gemv_k<<<NNODE, 256>>>(x, fcW, fcb, o_out);
}

// round 7
// speedup vs baseline: 9.2832x; 1.1432x over previous
#include <cuda_runtime.h>
#include <cuda_bf16.h>
#include <cuda_fp16.h>
#include <cstdint>

#define NNODE 4096
#define CDIM  768
#define HDIM  512
#define ODIM  50
#define OPAD  64

#define EPI_SIM  0
#define EPI_XW1T 1
#define EPI_H    2
#define EPI_HW2T 3
#define EPI_G    4

#define CAND_CAP 65536
#define FIXWIN 0.12f

// ---------------- device scratch (static: no allocations allowed) -------------
__device__ __align__(16) __nv_bfloat16 g_a01[(size_t)NNODE * NNODE];
__device__ __align__(16) __half        g_xf16[(size_t)NNODE * CDIM];
__device__ __align__(16) __nv_bfloat16 g_xbh[(size_t)NNODE * CDIM];
__device__ __align__(16) __nv_bfloat16 g_w1th[(size_t)HDIM * CDIM];
__device__ __align__(16) __nv_bfloat16 g_w2th[(size_t)OPAD * HDIM];
__device__ __align__(16) __nv_bfloat16 g_xw1th[(size_t)HDIM * NNODE];
__device__ __align__(16) __nv_bfloat16 g_hh[(size_t)NNODE * HDIM];
__device__ __align__(16) __nv_bfloat16 g_hw2th[(size_t)OPAD * NNODE];
__device__ __align__(16) float g_g[(size_t)NNODE * OPAD];
__device__ float g_b2p[OPAD];
__device__ float g_dinv[NNODE];
__device__ int   g_deg[NNODE];
__device__ int   g_lab[NNODE];
__device__ double g_s0d[CDIM], g_s1d[CDIM];
__device__ unsigned long long g_cnt;
__device__ float g_thr;
__device__ int   g_ncand;
__device__ int2  g_cand[CAND_CAP];

// ---------------- PTX helpers (all sm_80-compatible) ---------------------------
__device__ __forceinline__ uint32_t smem_u32(const void* p) {
    uint32_t a;
    asm("{ .reg .u64 t; cvta.to.shared.u64 t, %1; cvt.u32.u64 %0, t; }" : "=r"(a) : "l"(p));
    return a;
}
__device__ __forceinline__ void cp16(uint32_t d, const void* g) {
    asm volatile("cp.async.cg.shared.global [%0], [%1], 16;" :: "r"(d), "l"(g));
}
#define CP_COMMIT() asm volatile("cp.async.commit_group;" ::: "memory")
template<int N> __device__ __forceinline__ void cp_wait() {
    asm volatile("cp.async.wait_group %0;" :: "n"(N) : "memory");
}
__device__ __forceinline__ void ldm_x4(uint32_t* r, uint32_t addr) {
    asm volatile("ldmatrix.sync.aligned.m8n8.x4.shared.b16 {%0,%1,%2,%3}, [%4];"
        : "=r"(r[0]), "=r"(r[1]), "=r"(r[2]), "=r"(r[3]) : "r"(addr));
}
__device__ __forceinline__ void mma_bf16(float* c, const uint32_t* a, const uint32_t* b) {
    asm volatile(
        "mma.sync.aligned.m16n8k16.row.col.f32.bf16.bf16.f32 "
        "{%0,%1,%2,%3}, {%4,%5,%6,%7}, {%8,%9}, {%0,%1,%2,%3};"
        : "+f"(c[0]), "+f"(c[1]), "+f"(c[2]), "+f"(c[3])
        : "r"(a[0]), "r"(a[1]), "r"(a[2]), "r"(a[3]), "r"(b[0]), "r"(b[1]));
}
__device__ __forceinline__ void mma_fp16(float* c, const uint32_t* a, const uint32_t* b) {
    asm volatile(
        "mma.sync.aligned.m16n8k16.row.col.f32.f16.f16.f32 "
        "{%0,%1,%2,%3}, {%4,%5,%6,%7}, {%8,%9}, {%0,%1,%2,%3};"
        : "+f"(c[0]), "+f"(c[1]), "+f"(c[2]), "+f"(c[3])
        : "r"(a[0]), "r"(a[1]), "r"(a[2]), "r"(a[3]), "r"(b[0]), "r"(b[1]));
}

// ---------------- mma.sync GEMM: D[M,N] = A[M,K] * B[N,K]^T (single term) -----
// EPI_SIM: fused graph build — thr already known; emits a01/loss/deg/candidates.
template<int TN, bool FP16, int EPI>
__global__ void __launch_bounds__(256)
mma_gemm_k(const __nv_bfloat16* __restrict__ A0, const __nv_bfloat16* __restrict__ B0,
           int K, int lda, int ldb,
           float* __restrict__ fout, __nv_bfloat16* __restrict__ oh,
           const float* __restrict__ bias,
           float* __restrict__ lm, int write_loss)
{
    constexpr int WN = 32;
    constexpr int WM = (TN == 128) ? 64 : 32;
    constexpr int WX = TN / WN;
    constexpr int MI = WM / 16;
    constexpr int NJ = WN / 8;
    constexpr int ASTG = 128 * 128;
    constexpr int BSTG = TN * 128;
    constexpr int STG = ASTG + BSTG;

    extern __shared__ char smem[];
    __shared__ int s_degM[128];
    __shared__ int s_degN[128];
    const uint32_t sb = smem_u32(smem);
    const int tid = threadIdx.x;
    const int w = tid >> 5, lane = tid & 31;
    const int wm = (w / WX) * WM, wn = (w % WX) * WN;

    int bm, bn;
    bool diag = true;
    if (EPI == EPI_SIM) {
        int idx = blockIdx.x;
        int bi = 0;
        while (idx >= 32 - bi) { idx -= 32 - bi; bi++; }
        int bj = bi + idx;
        bm = bi * 128;
        bn = bj * 128;
        diag = (bi == bj);
    } else {
        bm = blockIdx.y * 128;
        bn = blockIdx.x * TN;
    }

    float acc[MI][NJ][4];
#pragma unroll
    for (int i = 0; i < MI; i++)
#pragma unroll
        for (int j = 0; j < NJ; j++)
#pragma unroll
            for (int q = 0; q < 4; q++) acc[i][j][q] = 0.f;

    const int kchunks = K >> 6;

    auto load_stage = [&](int s, int kc) {
        const uint32_t sA = sb + s * STG;
        const uint32_t sB = sA + ASTG;
#pragma unroll
        for (int i = 0; i < 4; i++) {
            int q = i * 256 + tid;
            int r = q >> 3, c = q & 7;
            cp16(sA + r * 128 + (((c ^ (r & 7)) << 4)),
                 A0 + (size_t)(bm + r) * lda + kc * 64 + c * 8);
        }
#pragma unroll
        for (int i = 0; i < TN / 32; i++) {
            int q = i * 256 + tid;
            int r = q >> 3, c = q & 7;
            cp16(sB + r * 128 + (((c ^ (r & 7)) << 4)),
                 B0 + (size_t)(bn + r) * ldb + kc * 64 + c * 8);
        }
        CP_COMMIT();
    };

    load_stage(0, 0);
    for (int ch = 0; ch < kchunks; ch++) {
        if (ch + 1 < kchunks) {
            load_stage((ch + 1) & 1, ch + 1);
            cp_wait<1>();
        } else {
            cp_wait<0>();
        }
        __syncthreads();

        const uint32_t sA = sb + (ch & 1) * STG;
        const uint32_t sB = sA + ASTG;
#pragma unroll
        for (int kk = 0; kk < 4; kk++) {
            uint32_t a[MI][4];
#pragma unroll
            for (int i = 0; i < MI; i++) {
                int r = wm + i * 16 + (lane & 15);
                int c = kk * 2 + (lane >> 4);
                ldm_x4(a[i], sA + r * 128 + (((c ^ (r & 7)) << 4)));
            }
            uint32_t b[NJ][2];
#pragma unroll
            for (int jj = 0; jj < NJ / 2; jj++) {
                int mat = lane >> 3;
                int tile = 2 * jj + (mat >> 1);
                int kh = mat & 1;
                int n = wn + tile * 8 + (lane & 7);
                int c = kk * 2 + kh;
                uint32_t r4[4];
                ldm_x4(r4, sB + n * 128 + (((c ^ (n & 7)) << 4)));
                b[2 * jj][0] = r4[0]; b[2 * jj][1] = r4[1];
                b[2 * jj + 1][0] = r4[2]; b[2 * jj + 1][1] = r4[3];
            }
#pragma unroll
            for (int i = 0; i < MI; i++)
#pragma unroll
                for (int j = 0; j < NJ; j++) {
                    if (FP16) mma_fp16(acc[i][j], a[i], b[j]);
                    else      mma_bf16(acc[i][j], a[i], b[j]);
                }
        }
        __syncthreads();
    }
    // pipeline smem dead; EPI_SIM off-diag reuses it as 128x128 bf16 mirror tile
    __nv_bfloat16* sT = reinterpret_cast<__nv_bfloat16*>(smem);
    if (EPI == EPI_SIM) {
        if (tid < 128) { s_degM[tid] = 0; s_degN[tid] = 0; }
        __syncthreads();
    }

    // -------- epilogue -------------------------------------------------------
    const int g4 = lane >> 2, t4 = lane & 3;
    const float thr = (EPI == EPI_SIM) ? g_thr : 0.f;
#pragma unroll
    for (int i = 0; i < MI; i++) {
#pragma unroll
        for (int p = 0; p < 2; p++) {
            const int ml = wm + i * 16 + g4 + p * 8;
            const int m = bm + ml;
            float dl = 1.f;
            int li = 0;
            if (EPI == EPI_SIM) li = g_lab[m];
            else dl = g_dinv[m];
#pragma unroll
            for (int j = 0; j < NJ; j++) {
                const int nl = wn + j * 8 + t4 * 2;   // even
                const int n = bn + nl;
                const float v0 = acc[i][j][2 * p + 0];
                const float v1 = acc[i][j][2 * p + 1];
                if (EPI == EPI_SIM) {
                    const bool same0 = (g_lab[n] == li) && (m != n);
                    const bool same1 = (g_lab[n + 1] == li) && (m != n + 1);
                    const bool e0 = same0 && (v0 <= thr);
                    const bool e1 = same1 && (v1 <= thr);
                    // a01 = A + I (direct store, both halves of the pair)
                    const float a0 = (e0 || m == n) ? 1.f : 0.f;
                    const float a1 = (e1 || m == n + 1) ? 1.f : 0.f;
                    *reinterpret_cast<__nv_bfloat162*>(g_a01 + (size_t)m * NNODE + n) =
                        __floats2bfloat162_rn(a0, a1);
                    // degree
                    atomicAdd(&s_degM[ml], (e0 ? 1 : 0) + (e1 ? 1 : 0));
                    if (!diag) {
                        if (e0) atomicAdd(&s_degN[nl], 1);
                        if (e1) atomicAdd(&s_degN[nl + 1], 1);
                    }
                    // borderline candidates (i<j), provisional decision in bit31
                    if (same0 && m < n && fabsf(v0 - thr) < FIXWIN) {
                        int pos = atomicAdd(&g_ncand, 1);
                        if (pos < CAND_CAP)
                            g_cand[pos] = make_int2(m, n | (e0 ? (int)0x80000000 : 0));
                    }
                    if (same1 && m < n + 1 && fabsf(v1 - thr) < FIXWIN) {
                        int pos = atomicAdd(&g_ncand, 1);
                        if (pos < CAND_CAP)
                            g_cand[pos] = make_int2(m, (n + 1) | (e1 ? (int)0x80000000 : 0));
                    }
                    // loss mask (upper triangle; lower memset to 0)
                    if (write_loss) {
                        if (!diag) {
                            *reinterpret_cast<float2*>(lm + (size_t)m * NNODE + n) =
                                make_float2(e0 ? 1.f : 0.f, e1 ? 1.f : 0.f);
                        } else {
                            if (m < n)     lm[(size_t)m * NNODE + n]     = e0 ? 1.f : 0.f;
                            if (m < n + 1) lm[(size_t)m * NNODE + n + 1] = e1 ? 1.f : 0.f;
                        }
                    }
                    // mirror a01 to lower triangle via smem transpose
                    if (!diag) {
                        const int swz = ((nl >> 1) & 3) << 3;   // even; same for nl, nl+1
                        sT[nl * 128 + (ml ^ swz)] = __float2bfloat16(a0);
                        sT[(nl + 1) * 128 + (ml ^ swz)] = __float2bfloat16(a1);
                    }
                } else if (EPI == EPI_XW1T || EPI == EPI_HW2T) {
                    oh[(size_t)n * NNODE + m] = __float2bfloat16(dl * v0);
                    oh[(size_t)(n + 1) * NNODE + m] = __float2bfloat16(dl * v1);
                } else if (EPI == EPI_H) {
                    float s0 = fmaxf(dl * v0 + bias[n], 0.f);
                    float s1 = fmaxf(dl * v1 + bias[n + 1], 0.f);
                    *reinterpret_cast<__nv_bfloat162*>(oh + (size_t)m * HDIM + n) =
                        __nv_bfloat162(__float2bfloat16(s0), __float2bfloat16(s1));
                } else { // EPI_G
                    *reinterpret_cast<float2*>(fout + (size_t)m * OPAD + n) =
                        make_float2(dl * v0 + bias[n], dl * v1 + bias[n + 1]);
                }
            }
        }
    }
    if (EPI == EPI_SIM) {
        __syncthreads();
        if (tid < 128) {
            atomicAdd(&g_deg[bm + tid], s_degM[tid]);
            if (!diag) atomicAdd(&g_deg[bn + tid], s_degN[tid]);
        }
        if (!diag) {   // coalesced mirror writeback (bf16 pairs)
            for (int q = tid; q < 128 * 64; q += 256) {
                const int nl = q >> 6, mp = (q & 63) * 2;
                const int swz = ((nl >> 1) & 3) << 3;
                __nv_bfloat162 u;
                u.x = sT[nl * 128 + (mp ^ swz)];
                u.y = sT[nl * 128 + ((mp + 1) ^ swz)];
                *reinterpret_cast<__nv_bfloat162*>(
                    g_a01 + (size_t)(bn + nl) * NNODE + bm + mp) = u;
            }
        }
    }
}

// ---------------- labels: detect int32 vs int64, normalize, cnt, zero state ---
__global__ void lab_k(const int* __restrict__ p) {
    __shared__ int sh[256];
    __shared__ int so[256];
    for (int i = threadIdx.x; i < CDIM; i += 256) { g_s0d[i] = 0.0; g_s1d[i] = 0.0; }
    for (int i = threadIdx.x; i < NNODE; i += 256) g_deg[i] = 0;
    int o = 0;
    for (int i = threadIdx.x; i < NNODE / 2; i += 256) o |= p[2 * i + 1];
    so[threadIdx.x] = o;
    __syncthreads();
    for (int off = 128; off > 0; off >>= 1) {
        if (threadIdx.x < off) so[threadIdx.x] |= so[threadIdx.x + off];
        __syncthreads();
    }
    const bool is32 = (so[0] != 0);
    int n1 = 0;
    for (int i = threadIdx.x; i < NNODE; i += 256) {
        int v = is32 ? p[i] : p[2 * i];
        g_lab[i] = v;
        n1 += (v != 0) ? 1 : 0;
    }
    sh[threadIdx.x] = n1;
    __syncthreads();
    for (int off = 128; off > 0; off >>= 1) {
        if (threadIdx.x < off) sh[threadIdx.x] += sh[threadIdx.x + off];
        __syncthreads();
    }
    if (threadIdx.x == 0) {
        unsigned long long c1 = (unsigned long long)sh[0];
        g_cnt = 2ULL * c1 * (unsigned long long)(NNODE - c1);
        g_ncand = 0;
    }
}

// ---------------- per-label column sums of x (exact threshold) ----------------
__global__ void lab_sum_k(const float* __restrict__ x) {
    const int b = blockIdx.x;
    const int t = threadIdx.x;
    float a0[3] = {0.f, 0.f, 0.f}, a1[3] = {0.f, 0.f, 0.f};
    for (int r = b * 16; r < b * 16 + 16; r++) {
        const float* row = x + (size_t)r * CDIM;
        const bool l1 = (g_lab[r] != 0);
#pragma unroll
        for (int q = 0; q < 3; q++) {
            float v = row[t + q * 256];
            if (l1) a1[q] += v; else a0[q] += v;
        }
    }
#pragma unroll
    for (int q = 0; q < 3; q++) {
        atomicAdd(&g_s0d[t + q * 256], (double)a0[q]);
        atomicAdd(&g_s1d[t + q * 256], (double)a1[q]);
    }
}

// thr = 2 * s0 . s1 / cnt (exact collapse of the cross-label sim sum)
__global__ void thr_dot_k() {
    __shared__ double sh[256];
    double s = 0.0;
    for (int c = threadIdx.x; c < CDIM; c += 256) s += g_s0d[c] * g_s1d[c];
    sh[threadIdx.x] = s;
    __syncthreads();
    for (int off = 128; off > 0; off >>= 1) {
        if (threadIdx.x < off) sh[threadIdx.x] += sh[threadIdx.x + off];
        __syncthreads();
    }
    if (threadIdx.x == 0)
        g_thr = (g_cnt > 0ULL) ? (float)(2.0 * sh[0] / (double)g_cnt) : 0.f;
}

// ---------------- x converts: fp16 (sim) + bf16 (xw1) -------------------------
__global__ void split_x_k(const float* __restrict__ x) {
    size_t tot = (size_t)NNODE * CDIM;
    for (size_t i = (size_t)blockIdx.x * blockDim.x + threadIdx.x; i < tot;
         i += (size_t)gridDim.x * blockDim.x) {
        float v = x[i];
        g_xf16[i] = __float2half(v);
        g_xbh[i] = __float2bfloat16(v);
    }
}

// ---------------- weights: transpose + bf16 + pad -----------------------------
__global__ void prep_w_k(const float* __restrict__ W1, const float* __restrict__ W2,
                         const float* __restrict__ b2) {
    size_t idx = (size_t)blockIdx.x * blockDim.x + threadIdx.x;
    size_t stride = (size_t)gridDim.x * blockDim.x;
    if (idx < OPAD) g_b2p[idx] = (idx < ODIM) ? b2[idx] : 0.f;
    size_t t1 = (size_t)HDIM * CDIM;
    for (size_t t = idx; t < t1; t += stride) {
        int n = (int)(t / CDIM), k = (int)(t % CDIM);
        g_w1th[t] = __float2bfloat16(W1[(size_t)k * HDIM + n]);
    }
    size_t t2 = (size_t)OPAD * HDIM;
    for (size_t t = idx; t < t2; t += stride) {
        int n = (int)(t / HDIM), k = (int)(t % HDIM);
        g_w2th[t] = __float2bfloat16((n < ODIM) ? W2[(size_t)k * ODIM + n] : 0.f);
    }
}

// ---------------- fixup: exact fp32 dot, warp per candidate; patch on flip ----
__global__ void fix_k(const float* __restrict__ x, float* __restrict__ lm, int wl) {
    int nc = g_ncand;
    if (nc > CAND_CAP) nc = CAND_CAP;
    const float thr = g_thr;
    const int gw = (blockIdx.x * blockDim.x + threadIdx.x) >> 5;
    const int lane = threadIdx.x & 31;
    const int nw = (gridDim.x * blockDim.x) >> 5;
    for (int cid = gw; cid < nc; cid += nw) {
        int2 c = g_cand[cid];
        const int i = c.x;
        const int j = c.y & 0x7FFFFFFF;
        const bool prov = (c.y < 0);
        const float4* xi = reinterpret_cast<const float4*>(x + (size_t)i * CDIM);
        const float4* xj = reinterpret_cast<const float4*>(x + (size_t)j * CDIM);
        float s = 0.f;
        for (int k = lane; k < CDIM / 4; k += 32) {
            float4 a = xi[k], b = xj[k];
            s += a.x * b.x + a.y * b.y + a.z * b.z + a.w * b.w;
        }
#pragma unroll
        for (int o = 16; o > 0; o >>= 1) s += __shfl_xor_sync(0xFFFFFFFFu, s, o);
        if (lane == 0) {
            const bool e = (s <= thr);
            if (e != prov) {
                const float av = e ? 1.f : 0.f;
                const __nv_bfloat16 ab = __float2bfloat16(av);
                g_a01[(size_t)i * NNODE + j] = ab;
                g_a01[(size_t)j * NNODE + i] = ab;
                if (wl) lm[(size_t)i * NNODE + j] = av;
                const int d = e ? 1 : -1;
                atomicAdd(&g_deg[i], d);
                atomicAdd(&g_deg[j], d);
            }
        }
    }
}

// ---------------- dinv from degrees -------------------------------------------
__global__ void dinv_k() {
    int i = blockIdx.x * blockDim.x + threadIdx.x;
    if (i < NNODE) g_dinv[i] = rsqrtf((float)(g_deg[i] + 1));
}

// ---------------- fused f_g + x copy + final GEMV -----------------------------
__global__ void fgout_k(const float* __restrict__ x, const float* __restrict__ fcW,
                        const float* __restrict__ fcb, float* __restrict__ out,
                        float* __restrict__ fg, float* __restrict__ xout, int full) {
    const int i = blockIdx.x;
    const int FDIM = CDIM + ODIM;
    const float* xr = x + (size_t)i * CDIM;
    float s = 0.f;
    for (int c = threadIdx.x; c < CDIM; c += 256) {
        float v = xr[c];
        s += v * fcW[c];
        if (full) {
            fg[(size_t)i * FDIM + c] = v;
            xout[(size_t)i * CDIM + c] = v;
        }
    }
    for (int o = threadIdx.x; o < ODIM; o += 256) {
        float v = g_g[(size_t)i * OPAD + o];
        s += v * fcW[CDIM + o];
        if (full) fg[(size_t)i * FDIM + CDIM + o] = v;
    }
    __shared__ float sh[256];
    sh[threadIdx.x] = s;
    __syncthreads();
    for (int off = 128; off > 0; off >>= 1) {
        if (threadIdx.x < off) sh[threadIdx.x] += sh[threadIdx.x + off];
        __syncthreads();
    }
    if (threadIdx.x == 0) out[i] = sh[0] + fcb[0];
}

// ---------------- launch ------------------------------------------------------
extern "C" void kernel_launch(void* const* d_in, const int* in_sizes, int n_in,
                              void* d_out, int out_size) {
    const float* x   = (const float*)d_in[0];
    const int*   lab = (const int*)d_in[1];
    const float* W1  = (const float*)d_in[2];
    const float* b1  = (const float*)d_in[3];
    const float* W2  = (const float*)d_in[4];
    const float* b2  = (const float*)d_in[5];
    const float* fcW = (const float*)d_in[6];
    const float* fcb = (const float*)d_in[7];
    (void)in_sizes; (void)n_in;

    const size_t SZ_OUT = NNODE;
    const size_t SZ_FG  = (size_t)NNODE * (CDIM + ODIM);
    const size_t SZ_LM  = (size_t)NNODE * NNODE;
    const size_t SZ_X   = (size_t)NNODE * CDIM;
    const bool full = ((size_t)out_size >= SZ_OUT + SZ_FG + SZ_LM + SZ_X);

    float* o_out = (float*)d_out;
    float* o_fg  = o_out + SZ_OUT;
    float* o_lm  = o_fg + SZ_FG;
    float* o_x   = o_lm + SZ_LM;

    __nv_bfloat16 *xbh, *w1th, *w2th, *xw1th, *hh, *hw2th, *a01;
    __half* xf16;
    float *gp, *b2pp;
    cudaGetSymbolAddress((void**)&xf16, g_xf16);
    cudaGetSymbolAddress((void**)&xbh, g_xbh);
    cudaGetSymbolAddress((void**)&w1th, g_w1th);
    cudaGetSymbolAddress((void**)&w2th, g_w2th);
    cudaGetSymbolAddress((void**)&xw1th, g_xw1th);
    cudaGetSymbolAddress((void**)&hh, g_hh);
    cudaGetSymbolAddress((void**)&hw2th, g_hw2th);
    cudaGetSymbolAddress((void**)&a01, g_a01);
    cudaGetSymbolAddress((void**)&gp, g_g);
    cudaGetSymbolAddress((void**)&b2pp, g_b2p);

    const int SM128 = 2 * (128 * 128 + 128 * 128);  // 65536
    const int SM64  = 2 * (128 * 128 + 64 * 128);   // 49152
    cudaFuncSetAttribute(mma_gemm_k<128, true,  EPI_SIM>,  cudaFuncAttributeMaxDynamicSharedMemorySize, SM128);
    cudaFuncSetAttribute(mma_gemm_k<128, false, EPI_XW1T>, cudaFuncAttributeMaxDynamicSharedMemorySize, SM128);
    cudaFuncSetAttribute(mma_gemm_k<128, false, EPI_H>,    cudaFuncAttributeMaxDynamicSharedMemorySize, SM128);
    cudaFuncSetAttribute(mma_gemm_k<64, false, EPI_HW2T>,  cudaFuncAttributeMaxDynamicSharedMemorySize, SM64);
    cudaFuncSetAttribute(mma_gemm_k<64, false, EPI_G>,     cudaFuncAttributeMaxDynamicSharedMemorySize, SM64);

    // 0. labels + converts + weight prep + exact threshold (before sim!)
    lab_k<<<1, 256>>>(lab);
    split_x_k<<<512, 256>>>(x);
    prep_w_k<<<256, 256>>>(W1, W2, b2);
    lab_sum_k<<<256, 256>>>(x);
    thr_dot_k<<<1, 256>>>();
    if (full) cudaMemsetAsync(o_lm, 0, SZ_LM * sizeof(float));

    // 1. fused sim + graph build (fp16 MMA, 528 upper-tri blocks):
    //    emits a01 (both triangles), loss_mask (upper), degrees, candidates.
    mma_gemm_k<128, true, EPI_SIM><<<528, 256, SM128>>>(
        (const __nv_bfloat16*)xf16, (const __nv_bfloat16*)xf16,
        CDIM, CDIM, CDIM, nullptr, nullptr, nullptr,
        full ? o_lm : nullptr, full ? 1 : 0);

    // 2. exact fp32 fixup: patch a01/lm/deg where the exact dot flips the edge
    fix_k<<<256, 256>>>(x, full ? o_lm : nullptr, full ? 1 : 0);
    dinv_k<<<16, 256>>>();

    // 3. xw1 = x @ W1; write (dinv_j * xw1)^T bf16   [512 x 4096]
    mma_gemm_k<128, false, EPI_XW1T><<<dim3(HDIM / 128, 32), 256, SM128>>>(
        xbh, w1th, CDIM, CDIM, CDIM, nullptr, xw1th, nullptr, nullptr, 0);

    // 4. h = relu(dinv_i * (a01 @ xw1t) + b1) bf16   [4096 x 512]
    mma_gemm_k<128, false, EPI_H><<<dim3(HDIM / 128, 32), 256, SM128>>>(
        a01, xw1th, NNODE, NNODE, NNODE, nullptr, hh, b1, nullptr, 0);

    // 5. hw2 = h @ W2p; write (dinv_j * hw2)^T bf16  [64 x 4096]
    mma_gemm_k<64, false, EPI_HW2T><<<dim3(1, 32), 256, SM64>>>(
        hh, w2th, HDIM, HDIM, HDIM, nullptr, hw2th, nullptr, nullptr, 0);

    // 6. g = dinv_i * (a01 @ hw2t) + b2p   [4096 x 64] fp32
    mma_gemm_k<64, false, EPI_G><<<dim3(1, 32), 256, SM64>>>(
        a01, hw2th, NNODE, NNODE, NNODE, gp, nullptr, b2pp, nullptr, 0);

    // 7. fused f_g + x copy + out GEMV
    fgout_k<<<NNODE, 256>>>(x, fcW, fcb, o_out, full ? o_fg : nullptr,
                            full ? o_x : nullptr, full ? 1 : 0);
}

// round 8
// speedup vs baseline: 9.4190x; 1.0146x over previous
#include <cuda_runtime.h>
#include <cuda_bf16.h>
#include <cuda_fp16.h>
#include <cstdint>

#define NNODE 4096
#define CDIM  768
#define HDIM  512
#define ODIM  50
#define OPAD  64

#define EPI_SIM  0
#define EPI_XW1T 1
#define EPI_H    2
#define EPI_HW2T 3
#define EPI_G    4

#define CAND_CAP 65536
#define FIXWIN 0.12f

// ---------------- device scratch (static: no allocations allowed) -------------
// All node-indexed arrays below live in SORTED space (label-0 nodes first,
// stable within label). g_perm maps sorted -> original.
__device__ __align__(16) __nv_bfloat16 g_a01[(size_t)NNODE * NNODE];
__device__ __align__(16) __half        g_xf16[(size_t)NNODE * CDIM];
__device__ __align__(16) __nv_bfloat16 g_xbh[(size_t)NNODE * CDIM];
__device__ __align__(16) __nv_bfloat16 g_w1th[(size_t)HDIM * CDIM];
__device__ __align__(16) __nv_bfloat16 g_w2th[(size_t)OPAD * HDIM];
__device__ __align__(16) __nv_bfloat16 g_xw1th[(size_t)HDIM * NNODE];
__device__ __align__(16) __nv_bfloat16 g_hh[(size_t)NNODE * HDIM];
__device__ __align__(16) __nv_bfloat16 g_hw2th[(size_t)OPAD * NNODE];
__device__ __align__(16) float g_g[(size_t)NNODE * OPAD];
__device__ float g_b2p[OPAD];
__device__ float g_dinv[NNODE];
__device__ int   g_deg[NNODE];
__device__ int   g_perm[NNODE];
__device__ int   g_c0;
__device__ double g_s0d[CDIM], g_s1d[CDIM];
__device__ unsigned long long g_cnt;
__device__ float g_thr;
__device__ int   g_ncand;
__device__ int2  g_cand[CAND_CAP];

// ---------------- PTX helpers (all sm_80-compatible) ---------------------------
__device__ __forceinline__ uint32_t smem_u32(const void* p) {
    uint32_t a;
    asm("{ .reg .u64 t; cvta.to.shared.u64 t, %1; cvt.u32.u64 %0, t; }" : "=r"(a) : "l"(p));
    return a;
}
__device__ __forceinline__ void cp16(uint32_t d, const void* g) {
    asm volatile("cp.async.cg.shared.global [%0], [%1], 16;" :: "r"(d), "l"(g));
}
#define CP_COMMIT() asm volatile("cp.async.commit_group;" ::: "memory")
template<int N> __device__ __forceinline__ void cp_wait() {
    asm volatile("cp.async.wait_group %0;" :: "n"(N) : "memory");
}
__device__ __forceinline__ void ldm_x4(uint32_t* r, uint32_t addr) {
    asm volatile("ldmatrix.sync.aligned.m8n8.x4.shared.b16 {%0,%1,%2,%3}, [%4];"
        : "=r"(r[0]), "=r"(r[1]), "=r"(r[2]), "=r"(r[3]) : "r"(addr));
}
__device__ __forceinline__ void mma_bf16(float* c, const uint32_t* a, const uint32_t* b) {
    asm volatile(
        "mma.sync.aligned.m16n8k16.row.col.f32.bf16.bf16.f32 "
        "{%0,%1,%2,%3}, {%4,%5,%6,%7}, {%8,%9}, {%0,%1,%2,%3};"
        : "+f"(c[0]), "+f"(c[1]), "+f"(c[2]), "+f"(c[3])
        : "r"(a[0]), "r"(a[1]), "r"(a[2]), "r"(a[3]), "r"(b[0]), "r"(b[1]));
}
__device__ __forceinline__ void mma_fp16(float* c, const uint32_t* a, const uint32_t* b) {
    asm volatile(
        "mma.sync.aligned.m16n8k16.row.col.f32.f16.f16.f32 "
        "{%0,%1,%2,%3}, {%4,%5,%6,%7}, {%8,%9}, {%0,%1,%2,%3};"
        : "+f"(c[0]), "+f"(c[1]), "+f"(c[2]), "+f"(c[3])
        : "r"(a[0]), "r"(a[1]), "r"(a[2]), "r"(a[3]), "r"(b[0]), "r"(b[1]));
}

// ---------------- mma.sync GEMM: D[M,N] = A[M,K] * B[N,K]^T (single term) -----
// EPI_SIM: fused graph build in sorted space. Cross-label tiles early-exit.
// EPI_H/EPI_G: K-range restricted to the row block's own label range.
template<int TN, bool FP16, int EPI>
__global__ void __launch_bounds__(256)
mma_gemm_k(const __nv_bfloat16* __restrict__ A0, const __nv_bfloat16* __restrict__ B0,
           int K, int lda, int ldb,
           float* __restrict__ fout, __nv_bfloat16* __restrict__ oh,
           const float* __restrict__ bias,
           float* __restrict__ lm, int write_loss)
{
    constexpr int WN = 32;
    constexpr int WM = (TN == 128) ? 64 : 32;
    constexpr int WX = TN / WN;
    constexpr int MI = WM / 16;
    constexpr int NJ = WN / 8;
    constexpr int ASTG = 128 * 128;
    constexpr int BSTG = TN * 128;
    constexpr int STG = ASTG + BSTG;

    const int c0 = g_c0;
    int bm, bn;
    bool diag = true;
    if (EPI == EPI_SIM) {
        int idx = blockIdx.x;
        int bi = 0;
        while (idx >= 32 - bi) { idx -= 32 - bi; bi++; }
        int bj = bi + idx;
        bm = bi * 128;
        bn = bj * 128;
        diag = (bi == bj);
        // entire tile is cross-label: a01/lm are zero (memset); nothing to do
        if (bm + 128 <= c0 && bn >= c0) return;
    } else {
        bm = blockIdx.y * 128;
        bn = blockIdx.x * TN;
    }

    extern __shared__ char smem[];
    __shared__ int s_degM[128];
    __shared__ int s_degN[128];
    const uint32_t sb = smem_u32(smem);
    const int tid = threadIdx.x;
    const int w = tid >> 5, lane = tid & 31;
    const int wm = (w / WX) * WM, wn = (w % WX) * WN;

    float acc[MI][NJ][4];
#pragma unroll
    for (int i = 0; i < MI; i++)
#pragma unroll
        for (int j = 0; j < NJ; j++)
#pragma unroll
            for (int q = 0; q < 4; q++) acc[i][j][q] = 0.f;

    // K-chunk range (block-diagonal skip for aggregation GEMMs)
    int cl = 0, chi = K >> 6;
    if (EPI == EPI_H || EPI == EPI_G) {
        if (bm + 128 <= c0)   chi = min(chi, (c0 + 63) >> 6);
        else if (bm >= c0)    cl = c0 >> 6;
    }
    const int nch = chi - cl;

    auto load_stage = [&](int s, int kc) {
        const uint32_t sA = sb + s * STG;
        const uint32_t sB = sA + ASTG;
#pragma unroll
        for (int i = 0; i < 4; i++) {
            int q = i * 256 + tid;
            int r = q >> 3, c = q & 7;
            cp16(sA + r * 128 + (((c ^ (r & 7)) << 4)),
                 A0 + (size_t)(bm + r) * lda + kc * 64 + c * 8);
        }
#pragma unroll
        for (int i = 0; i < TN / 32; i++) {
            int q = i * 256 + tid;
            int r = q >> 3, c = q & 7;
            cp16(sB + r * 128 + (((c ^ (r & 7)) << 4)),
                 B0 + (size_t)(bn + r) * ldb + kc * 64 + c * 8);
        }
        CP_COMMIT();
    };

    load_stage(0, cl);
    for (int t = 0; t < nch; t++) {
        if (t + 1 < nch) {
            load_stage((t + 1) & 1, cl + t + 1);
            cp_wait<1>();
        } else {
            cp_wait<0>();
        }
        __syncthreads();

        const uint32_t sA = sb + (t & 1) * STG;
        const uint32_t sB = sA + ASTG;
#pragma unroll
        for (int kk = 0; kk < 4; kk++) {
            uint32_t a[MI][4];
#pragma unroll
            for (int i = 0; i < MI; i++) {
                int r = wm + i * 16 + (lane & 15);
                int c = kk * 2 + (lane >> 4);
                ldm_x4(a[i], sA + r * 128 + (((c ^ (r & 7)) << 4)));
            }
            uint32_t b[NJ][2];
#pragma unroll
            for (int jj = 0; jj < NJ / 2; jj++) {
                int mat = lane >> 3;
                int tile = 2 * jj + (mat >> 1);
                int kh = mat & 1;
                int n = wn + tile * 8 + (lane & 7);
                int c = kk * 2 + kh;
                uint32_t r4[4];
                ldm_x4(r4, sB + n * 128 + (((c ^ (n & 7)) << 4)));
                b[2 * jj][0] = r4[0]; b[2 * jj][1] = r4[1];
                b[2 * jj + 1][0] = r4[2]; b[2 * jj + 1][1] = r4[3];
            }
#pragma unroll
            for (int i = 0; i < MI; i++)
#pragma unroll
                for (int j = 0; j < NJ; j++) {
                    if (FP16) mma_fp16(acc[i][j], a[i], b[j]);
                    else      mma_bf16(acc[i][j], a[i], b[j]);
                }
        }
        __syncthreads();
    }
    // pipeline smem dead; EPI_SIM off-diag reuses it as 128x128 bf16 mirror tile
    __nv_bfloat16* sT = reinterpret_cast<__nv_bfloat16*>(smem);
    if (EPI == EPI_SIM) {
        if (tid < 128) { s_degM[tid] = 0; s_degN[tid] = 0; }
        __syncthreads();
    }

    // -------- epilogue -------------------------------------------------------
    const int g4 = lane >> 2, t4 = lane & 3;
    const float thr = (EPI == EPI_SIM) ? g_thr : 0.f;
#pragma unroll
    for (int i = 0; i < MI; i++) {
#pragma unroll
        for (int p = 0; p < 2; p++) {
            const int ml = wm + i * 16 + g4 + p * 8;
            const int m = bm + ml;
            float dl = 1.f;
            int om = 0;
            if (EPI == EPI_SIM) { if (write_loss) om = g_perm[m]; }
            else dl = g_dinv[m];
            const bool mlab = (EPI == EPI_SIM) && (m < c0);
#pragma unroll
            for (int j = 0; j < NJ; j++) {
                const int nl = wn + j * 8 + t4 * 2;   // even
                const int n = bn + nl;
                const float v0 = acc[i][j][2 * p + 0];
                const float v1 = acc[i][j][2 * p + 1];
                if (EPI == EPI_SIM) {
                    const bool same0 = ((n < c0) == mlab) && (m != n);
                    const bool same1 = ((n + 1 < c0) == mlab) && (m != n + 1);
                    const bool e0 = same0 && (v0 <= thr);
                    const bool e1 = same1 && (v1 <= thr);
                    const float a0 = (e0 || m == n) ? 1.f : 0.f;
                    const float a1 = (e1 || m == n + 1) ? 1.f : 0.f;
                    *reinterpret_cast<__nv_bfloat162*>(g_a01 + (size_t)m * NNODE + n) =
                        __floats2bfloat162_rn(a0, a1);
                    atomicAdd(&s_degM[ml], (e0 ? 1 : 0) + (e1 ? 1 : 0));
                    if (!diag) {
                        if (e0) atomicAdd(&s_degN[nl], 1);
                        if (e1) atomicAdd(&s_degN[nl + 1], 1);
                    }
                    if (same0 && m < n && fabsf(v0 - thr) < FIXWIN) {
                        int pos = atomicAdd(&g_ncand, 1);
                        if (pos < CAND_CAP)
                            g_cand[pos] = make_int2(m, n | (e0 ? (int)0x80000000 : 0));
                    }
                    if (same1 && m < n + 1 && fabsf(v1 - thr) < FIXWIN) {
                        int pos = atomicAdd(&g_ncand, 1);
                        if (pos < CAND_CAP)
                            g_cand[pos] = make_int2(m, (n + 1) | (e1 ? (int)0x80000000 : 0));
                    }
                    // loss mask: write only edges (zeros come from memset);
                    // sorted m<n within a label <=> orig_m<orig_n (stable sort)
                    if (write_loss) {
                        if (e0 && m < n)     lm[(size_t)om * NNODE + g_perm[n]]     = 1.f;
                        if (e1 && m < n + 1) lm[(size_t)om * NNODE + g_perm[n + 1]] = 1.f;
                    }
                    if (!diag) {
                        const int swz = ((nl >> 1) & 3) << 3;
                        sT[nl * 128 + (ml ^ swz)] = __float2bfloat16(a0);
                        sT[(nl + 1) * 128 + (ml ^ swz)] = __float2bfloat16(a1);
                    }
                } else if (EPI == EPI_XW1T || EPI == EPI_HW2T) {
                    oh[(size_t)n * NNODE + m] = __float2bfloat16(dl * v0);
                    oh[(size_t)(n + 1) * NNODE + m] = __float2bfloat16(dl * v1);
                } else if (EPI == EPI_H) {
                    float s0 = fmaxf(dl * v0 + bias[n], 0.f);
                    float s1 = fmaxf(dl * v1 + bias[n + 1], 0.f);
                    *reinterpret_cast<__nv_bfloat162*>(oh + (size_t)m * HDIM + n) =
                        __nv_bfloat162(__float2bfloat16(s0), __float2bfloat16(s1));
                } else { // EPI_G
                    *reinterpret_cast<float2*>(fout + (size_t)m * OPAD + n) =
                        make_float2(dl * v0 + bias[n], dl * v1 + bias[n + 1]);
                }
            }
        }
    }
    if (EPI == EPI_SIM) {
        __syncthreads();
        if (tid < 128) {
            atomicAdd(&g_deg[bm + tid], s_degM[tid]);
            if (!diag) atomicAdd(&g_deg[bn + tid], s_degN[tid]);
        }
        if (!diag) {
            for (int q = tid; q < 128 * 64; q += 256) {
                const int nl = q >> 6, mp = (q & 63) * 2;
                const int swz = ((nl >> 1) & 3) << 3;
                __nv_bfloat162 u;
                u.x = sT[nl * 128 + (mp ^ swz)];
                u.y = sT[nl * 128 + ((mp + 1) ^ swz)];
                *reinterpret_cast<__nv_bfloat162*>(
                    g_a01 + (size_t)(bn + nl) * NNODE + bm + mp) = u;
            }
        }
    }
}

// ---------------- labels: dtype detect + stable label-sort permutation --------
__global__ void lab_k(const int* __restrict__ p) {
    __shared__ int so[256];
    __shared__ int sc[256];
    const int t = threadIdx.x;
    for (int i = t; i < CDIM; i += 256) { g_s0d[i] = 0.0; g_s1d[i] = 0.0; }
    for (int i = t; i < NNODE; i += 256) g_deg[i] = 0;
    int o = 0;
    for (int i = t; i < NNODE / 2; i += 256) o |= p[2 * i + 1];
    so[t] = o;
    __syncthreads();
    for (int off = 128; off > 0; off >>= 1) {
        if (t < off) so[t] |= so[t + off];
        __syncthreads();
    }
    const bool is32 = (so[0] != 0);
    const int base = t * 16;
    int lv[16];
    int z = 0;
    for (int k = 0; k < 16; k++) {
        int v = is32 ? p[base + k] : p[2 * (base + k)];
        lv[k] = v;
        z += (v == 0) ? 1 : 0;
    }
    sc[t] = z;
    __syncthreads();
    for (int off = 1; off < 256; off <<= 1) {   // inclusive Hillis-Steele scan
        int val = (t >= off) ? sc[t - off] : 0;
        __syncthreads();
        sc[t] += val;
        __syncthreads();
    }
    const int c0 = sc[255];
    int p0 = sc[t] - z;                 // zeros before my chunk
    int p1 = c0 + (base - (sc[t] - z)); // ones before my chunk
    for (int k = 0; k < 16; k++) {
        if (lv[k] == 0) g_perm[p0++] = base + k;
        else            g_perm[p1++] = base + k;
    }
    if (t == 0) {
        g_c0 = c0;
        unsigned long long cz = (unsigned long long)c0;
        g_cnt = 2ULL * cz * (unsigned long long)(NNODE - c0);
        g_ncand = 0;
    }
}

// ---------------- fused: permuted x converts + per-label column sums ----------
__global__ void split_x_k(const float* __restrict__ x) {
    const int b = blockIdx.x;           // 1024 blocks x 4 rows
    const int t = threadIdx.x;
    const int c0 = g_c0;
    float a0[3] = {0.f, 0.f, 0.f}, a1[3] = {0.f, 0.f, 0.f};
    for (int s = b * 4; s < b * 4 + 4; s++) {
        const int orig = g_perm[s];
        const float* row = x + (size_t)orig * CDIM;
        const bool l1 = (s >= c0);
#pragma unroll
        for (int q = 0; q < 3; q++) {
            const int col = t + q * 256;
            float v = row[col];
            g_xf16[(size_t)s * CDIM + col] = __float2half(v);
            g_xbh[(size_t)s * CDIM + col] = __float2bfloat16(v);
            if (l1) a1[q] += v; else a0[q] += v;
        }
    }
#pragma unroll
    for (int q = 0; q < 3; q++) {
        atomicAdd(&g_s0d[t + q * 256], (double)a0[q]);
        atomicAdd(&g_s1d[t + q * 256], (double)a1[q]);
    }
}

// thr = 2 * s0 . s1 / cnt (exact collapse of the cross-label sim sum)
__global__ void thr_dot_k() {
    __shared__ double sh[256];
    double s = 0.0;
    for (int c = threadIdx.x; c < CDIM; c += 256) s += g_s0d[c] * g_s1d[c];
    sh[threadIdx.x] = s;
    __syncthreads();
    for (int off = 128; off > 0; off >>= 1) {
        if (threadIdx.x < off) sh[threadIdx.x] += sh[threadIdx.x + off];
        __syncthreads();
    }
    if (threadIdx.x == 0)
        g_thr = (g_cnt > 0ULL) ? (float)(2.0 * sh[0] / (double)g_cnt) : 0.f;
}

// ---------------- weights: transpose + bf16 + pad -----------------------------
__global__ void prep_w_k(const float* __restrict__ W1, const float* __restrict__ W2,
                         const float* __restrict__ b2) {
    size_t idx = (size_t)blockIdx.x * blockDim.x + threadIdx.x;
    size_t stride = (size_t)gridDim.x * blockDim.x;
    if (idx < OPAD) g_b2p[idx] = (idx < ODIM) ? b2[idx] : 0.f;
    size_t t1 = (size_t)HDIM * CDIM;
    for (size_t t = idx; t < t1; t += stride) {
        int n = (int)(t / CDIM), k = (int)(t % CDIM);
        g_w1th[t] = __float2bfloat16(W1[(size_t)k * HDIM + n]);
    }
    size_t t2 = (size_t)OPAD * HDIM;
    for (size_t t = idx; t < t2; t += stride) {
        int n = (int)(t / HDIM), k = (int)(t % HDIM);
        g_w2th[t] = __float2bfloat16((n < ODIM) ? W2[(size_t)k * ODIM + n] : 0.f);
    }
}

// ---------------- fixup: exact fp32 dot, warp per candidate; patch on flip ----
__global__ void fix_k(const float* __restrict__ x, float* __restrict__ lm, int wl) {
    int nc = g_ncand;
    if (nc > CAND_CAP) nc = CAND_CAP;
    const float thr = g_thr;
    const int gw = (blockIdx.x * blockDim.x + threadIdx.x) >> 5;
    const int lane = threadIdx.x & 31;
    const int nw = (gridDim.x * blockDim.x) >> 5;
    for (int cid = gw; cid < nc; cid += nw) {
        int2 c = g_cand[cid];
        const int i = c.x;                       // sorted
        const int j = c.y & 0x7FFFFFFF;          // sorted, i<j
        const bool prov = (c.y < 0);
        const int oi = g_perm[i], oj = g_perm[j];
        const float4* xi = reinterpret_cast<const float4*>(x + (size_t)oi * CDIM);
        const float4* xj = reinterpret_cast<const float4*>(x + (size_t)oj * CDIM);
        float s = 0.f;
        for (int k = lane; k < CDIM / 4; k += 32) {
            float4 a = xi[k], b = xj[k];
            s += a.x * b.x + a.y * b.y + a.z * b.z + a.w * b.w;
        }
#pragma unroll
        for (int o = 16; o > 0; o >>= 1) s += __shfl_xor_sync(0xFFFFFFFFu, s, o);
        if (lane == 0) {
            const bool e = (s <= thr);
            if (e != prov) {
                const float av = e ? 1.f : 0.f;
                const __nv_bfloat16 ab = __float2bfloat16(av);
                g_a01[(size_t)i * NNODE + j] = ab;
                g_a01[(size_t)j * NNODE + i] = ab;
                if (wl) lm[(size_t)oi * NNODE + oj] = av;
                const int d = e ? 1 : -1;
                atomicAdd(&g_deg[i], d);
                atomicAdd(&g_deg[j], d);
            }
        }
    }
}

// ---------------- dinv from degrees -------------------------------------------
__global__ void dinv_k() {
    int i = blockIdx.x * blockDim.x + threadIdx.x;
    if (i < NNODE) g_dinv[i] = rsqrtf((float)(g_deg[i] + 1));
}

// ---------------- fused f_g + x copy + final GEMV (permuted writeback) --------
__global__ void fgout_k(const float* __restrict__ x, const float* __restrict__ fcW,
                        const float* __restrict__ fcb, float* __restrict__ out,
                        float* __restrict__ fg, float* __restrict__ xout, int full) {
    const int s = blockIdx.x;            // sorted node
    const int orig = g_perm[s];
    const int FDIM = CDIM + ODIM;
    const float* xr = x + (size_t)orig * CDIM;
    float acc = 0.f;
    for (int c = threadIdx.x; c < CDIM; c += 256) {
        float v = xr[c];
        acc += v * fcW[c];
        if (full) {
            fg[(size_t)orig * FDIM + c] = v;
            xout[(size_t)orig * CDIM + c] = v;
        }
    }
    for (int o = threadIdx.x; o < ODIM; o += 256) {
        float v = g_g[(size_t)s * OPAD + o];
        acc += v * fcW[CDIM + o];
        if (full) fg[(size_t)orig * FDIM + CDIM + o] = v;
    }
    __shared__ float sh[256];
    sh[threadIdx.x] = acc;
    __syncthreads();
    for (int off = 128; off > 0; off >>= 1) {
        if (threadIdx.x < off) sh[threadIdx.x] += sh[threadIdx.x + off];
        __syncthreads();
    }
    if (threadIdx.x == 0) out[orig] = sh[0] + fcb[0];
}

// ---------------- launch ------------------------------------------------------
extern "C" void kernel_launch(void* const* d_in, const int* in_sizes, int n_in,
                              void* d_out, int out_size) {
    const float* x   = (const float*)d_in[0];
    const int*   lab = (const int*)d_in[1];
    const float* W1  = (const float*)d_in[2];
    const float* b1  = (const float*)d_in[3];
    const float* W2  = (const float*)d_in[4];
    const float* b2  = (const float*)d_in[5];
    const float* fcW = (const float*)d_in[6];
    const float* fcb = (const float*)d_in[7];
    (void)in_sizes; (void)n_in;

    const size_t SZ_OUT = NNODE;
    const size_t SZ_FG  = (size_t)NNODE * (CDIM + ODIM);
    const size_t SZ_LM  = (size_t)NNODE * NNODE;
    const size_t SZ_X   = (size_t)NNODE * CDIM;
    const bool full = ((size_t)out_size >= SZ_OUT + SZ_FG + SZ_LM + SZ_X);

    float* o_out = (float*)d_out;
    float* o_fg  = o_out + SZ_OUT;
    float* o_lm  = o_fg + SZ_FG;
    float* o_x   = o_lm + SZ_LM;

    __nv_bfloat16 *xbh, *w1th, *w2th, *xw1th, *hh, *hw2th, *a01;
    __half* xf16;
    float *gp, *b2pp;
    cudaGetSymbolAddress((void**)&xf16, g_xf16);
    cudaGetSymbolAddress((void**)&xbh, g_xbh);
    cudaGetSymbolAddress((void**)&w1th, g_w1th);
    cudaGetSymbolAddress((void**)&w2th, g_w2th);
    cudaGetSymbolAddress((void**)&xw1th, g_xw1th);
    cudaGetSymbolAddress((void**)&hh, g_hh);
    cudaGetSymbolAddress((void**)&hw2th, g_hw2th);
    cudaGetSymbolAddress((void**)&a01, g_a01);
    cudaGetSymbolAddress((void**)&gp, g_g);
    cudaGetSymbolAddress((void**)&b2pp, g_b2p);

    const int SM128 = 2 * (128 * 128 + 128 * 128);  // 65536
    const int SM64  = 2 * (128 * 128 + 64 * 128);   // 49152
    cudaFuncSetAttribute(mma_gemm_k<128, true,  EPI_SIM>,  cudaFuncAttributeMaxDynamicSharedMemorySize, SM128);
    cudaFuncSetAttribute(mma_gemm_k<128, false, EPI_XW1T>, cudaFuncAttributeMaxDynamicSharedMemorySize, SM128);
    cudaFuncSetAttribute(mma_gemm_k<128, false, EPI_H>,    cudaFuncAttributeMaxDynamicSharedMemorySize, SM128);
    cudaFuncSetAttribute(mma_gemm_k<64, false, EPI_HW2T>,  cudaFuncAttributeMaxDynamicSharedMemorySize, SM64);
    cudaFuncSetAttribute(mma_gemm_k<64, false, EPI_G>,     cudaFuncAttributeMaxDynamicSharedMemorySize, SM64);

    // 0. labels + permutation; permuted converts fused with label sums; thr
    lab_k<<<1, 256>>>(lab);
    split_x_k<<<1024, 256>>>(x);
    prep_w_k<<<256, 256>>>(W1, W2, b2);
    thr_dot_k<<<1, 256>>>();
    cudaMemsetAsync(a01, 0, (size_t)NNODE * NNODE * sizeof(__nv_bfloat16));
    if (full) cudaMemsetAsync(o_lm, 0, SZ_LM * sizeof(float));

    // 1. fused sim + graph build (fp16 MMA, sorted space; cross-label tiles skip)
    mma_gemm_k<128, true, EPI_SIM><<<528, 256, SM128>>>(
        (const __nv_bfloat16*)xf16, (const __nv_bfloat16*)xf16,
        CDIM, CDIM, CDIM, nullptr, nullptr, nullptr,
        full ? o_lm : nullptr, full ? 1 : 0);

    // 2. exact fp32 fixup + dinv
    fix_k<<<256, 256>>>(x, full ? o_lm : nullptr, full ? 1 : 0);
    dinv_k<<<16, 256>>>();

    // 3. xw1 = x @ W1; write (dinv_j * xw1)^T bf16   [512 x 4096] (sorted)
    mma_gemm_k<128, false, EPI_XW1T><<<dim3(HDIM / 128, 32), 256, SM128>>>(
        xbh, w1th, CDIM, CDIM, CDIM, nullptr, xw1th, nullptr, nullptr, 0);

    // 4. h = relu(dinv_i * (a01 @ xw1t) + b1) bf16 [4096 x 512] (K block-diag)
    mma_gemm_k<128, false, EPI_H><<<dim3(HDIM / 128, 32), 256, SM128>>>(
        a01, xw1th, NNODE, NNODE, NNODE, nullptr, hh, b1, nullptr, 0);

    // 5. hw2 = h @ W2p; write (dinv_j * hw2)^T bf16  [64 x 4096]
    mma_gemm_k<64, false, EPI_HW2T><<<dim3(1, 32), 256, SM64>>>(
        hh, w2th, HDIM, HDIM, HDIM, nullptr, hw2th, nullptr, nullptr, 0);

    // 6. g = dinv_i * (a01 @ hw2t) + b2p [4096 x 64] fp32 (K block-diag)
    mma_gemm_k<64, false, EPI_G><<<dim3(1, 32), 256, SM64>>>(
        a01, hw2th, NNODE, NNODE, NNODE, gp, nullptr, b2pp, nullptr, 0);

    // 7. fused f_g + x copy + out GEMV (permuted writeback)
    fgout_k<<<NNODE, 256>>>(x, fcW, fcb, o_out, full ? o_fg : nullptr,
                            full ? o_x : nullptr, full ? 1 : 0);
}